// round 4
// baseline (speedup 1.0000x reference)
#include <cuda_runtime.h>
#include <cuda_bf16.h>
#include <cstdint>
#include <math.h>

// ---------------- problem constants ----------------
#define NB    2
#define SEQ   2048
#define NTOK  (NB*SEQ)          // 4096
#define DIN   512
#define NH    8
#define DH    64
#define QOFF  0
#define KOFF  512
#define VOFF  1024
#define QKVN  5120
#define DVH   512
#define DEXP  2048

typedef __nv_bfloat16 bf16;

// ---------------- scratch (device globals) ----------------
__device__ bf16  g_xn_h [NTOK * (long)DIN];
__device__ bf16  g_xn_l [NTOK * (long)DIN];
__device__ bf16  g_Wqkv_h[(long)QKVN * DIN];   // [N][K]
__device__ bf16  g_Wqkv_l[(long)QKVN * DIN];
__device__ bf16  g_Wm_h [(long)DIN * (NH*DVH)];
__device__ bf16  g_Wm_l [(long)DIN * (NH*DVH)];
__device__ bf16  g_W1_h [(long)DEXP * DIN];
__device__ bf16  g_W1_l [(long)DEXP * DIN];
__device__ bf16  g_W2_h [(long)DIN * DEXP];
__device__ bf16  g_W2_l [(long)DIN * DEXP];
__device__ bf16  g_qkv_h[NTOK * (long)QKVN];
__device__ bf16  g_qkv_l[NTOK * (long)QKVN];
__device__ bf16  g_vT_h [(long)NB*NH*DVH*SEQ];
__device__ bf16  g_vT_l [(long)NB*NH*DVH*SEQ];
__device__ float g_S    [(long)NB*NH*SEQ*SEQ];
__device__ bf16  g_P_h  [(long)NB*NH*SEQ*SEQ];
__device__ bf16  g_P_l  [(long)NB*NH*SEQ*SEQ];
__device__ bf16  g_ao_h [NTOK * (long)(NH*DVH)];
__device__ bf16  g_ao_l [NTOK * (long)(NH*DVH)];
__device__ float g_x2   [NTOK * (long)DIN];
__device__ bf16  g_x2n_h[NTOK * (long)DIN];
__device__ bf16  g_x2n_l[NTOK * (long)DIN];
__device__ bf16  g_h_h  [NTOK * (long)DEXP];
__device__ bf16  g_h_l  [NTOK * (long)DEXP];

// ---------------- helpers ----------------
__device__ __forceinline__ uint32_t smem_u32(const void* p) {
    uint32_t a;
    asm("{ .reg .u64 t; cvta.to.shared.u64 t, %1; cvt.u32.u64 %0, t; }" : "=r"(a) : "l"(p));
    return a;
}
__device__ __forceinline__ void ldx4(uint32_t* r, uint32_t a) {
    asm volatile("ldmatrix.sync.aligned.m8n8.x4.shared.b16 {%0,%1,%2,%3}, [%4];"
                 : "=r"(r[0]), "=r"(r[1]), "=r"(r[2]), "=r"(r[3]) : "r"(a));
}
__device__ __forceinline__ void mma16816(float* d, const uint32_t* a, const uint32_t* b) {
    asm volatile("mma.sync.aligned.m16n8k16.row.col.f32.bf16.bf16.f32 "
                 "{%0,%1,%2,%3}, {%4,%5,%6,%7}, {%8,%9}, {%0,%1,%2,%3};"
                 : "+f"(d[0]), "+f"(d[1]), "+f"(d[2]), "+f"(d[3])
                 : "r"(a[0]), "r"(a[1]), "r"(a[2]), "r"(a[3]), "r"(b[0]), "r"(b[1]));
}
__device__ __forceinline__ void cpa16(uint32_t dst, const void* src) {
    asm volatile("cp.async.cg.shared.global [%0], [%1], 16;" :: "r"(dst), "l"(src));
}
#define CP_COMMIT() asm volatile("cp.async.commit_group;")

__device__ __forceinline__ void split2(float x, float y, uint32_t& h, uint32_t& l) {
    __nv_bfloat162 hb = __float22bfloat162_rn(make_float2(x, y));
    uint32_t u = *(uint32_t*)&hb;
    float h0 = __uint_as_float(u << 16);
    float h1 = __uint_as_float(u & 0xFFFF0000u);
    __nv_bfloat162 lb = __float22bfloat162_rn(make_float2(x - h0, y - h1));
    h = u;
    l = *(uint32_t*)&lb;
}
__device__ __forceinline__ void split4(float4 v, uint2& h, uint2& l) {
    split2(v.x, v.y, h.x, l.x);
    split2(v.z, v.w, h.y, l.y);
}

// ---------------- split+transpose for weights: fp32 [R][C] -> hi/lo [C][R] --
__global__ void splitT(const float* __restrict__ in, bf16* __restrict__ oh,
                       bf16* __restrict__ ol, int R, int C) {
    __shared__ float t[32][33];
    int c0 = blockIdx.x * 32, r0 = blockIdx.y * 32;
    int tx = threadIdx.x, ty = threadIdx.y;
    #pragma unroll
    for (int j = 0; j < 4; j++)
        t[ty + j*8][tx] = in[(long)(r0 + ty + j*8) * C + c0 + tx];
    __syncthreads();
    #pragma unroll
    for (int j = 0; j < 4; j++) {
        float v = t[tx][ty + j*8];
        bf16 h = __float2bfloat16_rn(v);
        long o = (long)(c0 + ty + j*8) * R + r0 + tx;
        oh[o] = h;
        ol[o] = __float2bfloat16_rn(v - __bfloat162float(h));
    }
}

// ---------------- V transpose (bf16): qkv V section -> [bh][dvh][seq] ------
__global__ void vtrans(const bf16* __restrict__ qh, const bf16* __restrict__ ql,
                       bf16* __restrict__ vh, bf16* __restrict__ vl) {
    __shared__ uint16_t th[32][33], tl[32][33];
    int bh = blockIdx.z, b = bh >> 3, hd = bh & 7;
    int t0 = blockIdx.x * 32, c0 = blockIdx.y * 32;
    int tx = threadIdx.x, ty = threadIdx.y;
    const long inb = (long)b * SEQ * QKVN + VOFF + hd * DVH;
    #pragma unroll
    for (int j = 0; j < 4; j++) {
        long src = inb + (long)(t0 + ty + j*8) * QKVN + c0 + tx;
        th[ty + j*8][tx] = ((const uint16_t*)qh)[src];
        tl[ty + j*8][tx] = ((const uint16_t*)ql)[src];
    }
    __syncthreads();
    const long outb = (long)bh * DVH * SEQ;
    #pragma unroll
    for (int j = 0; j < 4; j++) {
        long dst = outb + (long)(c0 + ty + j*8) * SEQ + t0 + tx;
        ((uint16_t*)vh)[dst] = th[tx][ty + j*8];
        ((uint16_t*)vl)[dst] = tl[tx][ty + j*8];
    }
}

// ---------------- LayerNorm -> hi/lo bf16 ----------------
__global__ void ln_split(const float* __restrict__ x, const float* __restrict__ g,
                         const float* __restrict__ bta, bf16* __restrict__ oh,
                         bf16* __restrict__ ol) {
    __shared__ float red[2][4];
    long row = blockIdx.x;
    const float* xr = x + row * DIN;
    int t = threadIdx.x;
    float4 v = ((const float4*)xr)[t];
    float s  = v.x + v.y + v.z + v.w;
    float ss = v.x*v.x + v.y*v.y + v.z*v.z + v.w*v.w;
    #pragma unroll
    for (int off = 16; off > 0; off >>= 1) {
        s  += __shfl_down_sync(0xffffffffu, s,  off);
        ss += __shfl_down_sync(0xffffffffu, ss, off);
    }
    int warp = t >> 5, lane = t & 31;
    if (lane == 0) { red[0][warp] = s; red[1][warp] = ss; }
    __syncthreads();
    if (t == 0) {
        float S0 = red[0][0] + red[0][1] + red[0][2] + red[0][3];
        float S1 = red[1][0] + red[1][1] + red[1][2] + red[1][3];
        float mu  = S0 * (1.0f/DIN);
        float var = S1 * (1.0f/DIN) - mu*mu;
        red[0][0] = mu;
        red[1][0] = rsqrtf(var + 1e-5f);
    }
    __syncthreads();
    float mu = red[0][0], inv = red[1][0];
    float4 gg = ((const float4*)g)[t];
    float4 bb = ((const float4*)bta)[t];
    float4 r;
    r.x = (v.x - mu) * inv * gg.x + bb.x;
    r.y = (v.y - mu) * inv * gg.y + bb.y;
    r.z = (v.z - mu) * inv * gg.z + bb.z;
    r.w = (v.w - mu) * inv * gg.w + bb.w;
    uint2 h, l;
    split4(r, h, l);
    ((uint2*)(oh + row * DIN))[t] = h;
    ((uint2*)(ol + row * DIN))[t] = l;
}

// ---------------- softmax -> hi/lo bf16 P ----------------
__global__ void softmax_split(const float* __restrict__ S, bf16* __restrict__ Ph,
                              bf16* __restrict__ Pl) {
    __shared__ float red[8];
    long row = blockIdx.x;
    const float* r = S + row * (long)SEQ;
    int t = threadIdx.x;
    float4 a = ((const float4*)r)[t];
    float4 b = ((const float4*)r)[t + 256];
    float m = fmaxf(fmaxf(fmaxf(a.x,a.y),fmaxf(a.z,a.w)),
                    fmaxf(fmaxf(b.x,b.y),fmaxf(b.z,b.w)));
    #pragma unroll
    for (int off = 16; off > 0; off >>= 1)
        m = fmaxf(m, __shfl_xor_sync(0xffffffffu, m, off));
    int warp = t >> 5, lane = t & 31;
    if (lane == 0) red[warp] = m;
    __syncthreads();
    m = red[0];
    #pragma unroll
    for (int i = 1; i < 8; i++) m = fmaxf(m, red[i]);
    a.x = __expf(a.x - m); a.y = __expf(a.y - m); a.z = __expf(a.z - m); a.w = __expf(a.w - m);
    b.x = __expf(b.x - m); b.y = __expf(b.y - m); b.z = __expf(b.z - m); b.w = __expf(b.w - m);
    float s = a.x+a.y+a.z+a.w + b.x+b.y+b.z+b.w;
    #pragma unroll
    for (int off = 16; off > 0; off >>= 1)
        s += __shfl_xor_sync(0xffffffffu, s, off);
    __syncthreads();
    if (lane == 0) red[warp] = s;
    __syncthreads();
    s = red[0];
    #pragma unroll
    for (int i = 1; i < 8; i++) s += red[i];
    float inv = 1.0f / s;
    a.x *= inv; a.y *= inv; a.z *= inv; a.w *= inv;
    b.x *= inv; b.y *= inv; b.z *= inv; b.w *= inv;
    uint2 h0, l0, h1, l1;
    split4(a, h0, l0);
    split4(b, h1, l1);
    ((uint2*)(Ph + row * SEQ))[t]       = h0;
    ((uint2*)(Pl + row * SEQ))[t]       = l0;
    ((uint2*)(Ph + row * SEQ))[t + 256] = h1;
    ((uint2*)(Pl + row * SEQ))[t + 256] = l1;
}

// ---------------- HMMA pre-split bf16 GEMM ----------------
// C[M,N] = alpha * (Ah+Al)[M,K] @ (Bh+Bl)[N,K]^T  (3-term)
// A,B: hi/lo bf16, row-major [rows][K]. SMEM padded stride 40 elems (80B).
// CTA 128x128, 8 warps 2x4, warp 64x32, BK=32, cp.async double-buffer.
#define STAGE    40960
#define GSMEM_SZ (2 * STAGE)   // 81920

template<bool BIAS, bool RES, bool SWISH, bool SPLITOUT>
__global__ void __launch_bounds__(256, 2)
bf_gemm(const bf16* __restrict__ Ah, const bf16* __restrict__ Al,
        const bf16* __restrict__ Bh, const bf16* __restrict__ Bl,
        float* __restrict__ Cf, bf16* __restrict__ Ch, bf16* __restrict__ Cl,
        const float* __restrict__ bias, const float* __restrict__ res,
        int K, int lda, int ldb, int ldc,
        long sA1, long sA2, long sB1, long sB2, long sC1, long sC2,
        int zdiv, float alpha)
{
    extern __shared__ char sm[];
    const uint32_t smb = smem_u32(sm);
    const int tid = threadIdx.x, wid = tid >> 5, lane = tid & 31;
    const int wm = wid & 1, wn = wid >> 1;

    int z = blockIdx.z, z1 = z / zdiv, z2 = z - z1 * zdiv;
    Ah += z1 * sA1 + (long)z2 * sA2;
    Al += z1 * sA1 + (long)z2 * sA2;
    Bh += z1 * sB1 + (long)z2 * sB2;
    Bl += z1 * sB1 + (long)z2 * sB2;
    const long coff = z1 * sC1 + (long)z2 * sC2;
    const long bm0 = (long)blockIdx.y * 128;
    const long bn0 = (long)blockIdx.x * 128;

    const int rr = tid >> 1;          // row 0..127
    const int pq = (tid & 1) << 4;    // k element offset 0 or 16

    auto issue = [&](int k0, int buf) {
        const uint32_t base = smb + buf * STAGE;
        const bf16* as  = Ah + (bm0 + rr) * (long)lda + k0 + pq;
        const bf16* asl = Al + (bm0 + rr) * (long)lda + k0 + pq;
        uint32_t da = base + rr * 80 + pq * 2;
        cpa16(da, as);              cpa16(da + 16, as + 8);
        cpa16(da + 10240, asl);     cpa16(da + 10240 + 16, asl + 8);
        const bf16* bs  = Bh + (bn0 + rr) * (long)ldb + k0 + pq;
        const bf16* bsl = Bl + (bn0 + rr) * (long)ldb + k0 + pq;
        uint32_t db = base + 20480 + rr * 80 + pq * 2;
        cpa16(db, bs);              cpa16(db + 16, bs + 8);
        cpa16(db + 10240, bsl);     cpa16(db + 10240 + 16, bsl + 8);
    };

    float acc[4][4][4];
    #pragma unroll
    for (int i = 0; i < 4; i++)
        #pragma unroll
        for (int j = 0; j < 4; j++)
            #pragma unroll
            for (int t = 0; t < 4; t++) acc[i][j][t] = 0.0f;

    auto mma_chunk = [&](int buf) {
        const uint32_t base = smb + buf * STAGE;
        #pragma unroll
        for (int ks = 0; ks < 2; ks++) {
            const int kk = ks * 16;
            uint32_t bh[4][2], bl[4][2];
            #pragma unroll
            for (int p = 0; p < 2; p++) {
                uint32_t bd = base + 20480 + (wn * 32 + p * 16 + (lane & 15)) * 80
                                   + (kk + (lane >> 4) * 8) * 2;
                uint32_t r[4];
                ldx4(r, bd);
                bh[2*p][0] = r[0]; bh[2*p][1] = r[2];
                bh[2*p+1][0] = r[1]; bh[2*p+1][1] = r[3];
                ldx4(r, bd + 10240);
                bl[2*p][0] = r[0]; bl[2*p][1] = r[2];
                bl[2*p+1][0] = r[1]; bl[2*p+1][1] = r[3];
            }
            #pragma unroll
            for (int mi = 0; mi < 4; mi++) {
                uint32_t ah[4], al[4];
                uint32_t ad = base + (wm * 64 + mi * 16 + (lane & 15)) * 80
                                   + (kk + (lane >> 4) * 8) * 2;
                ldx4(ah, ad);
                ldx4(al, ad + 10240);
                #pragma unroll
                for (int ni = 0; ni < 4; ni++) {
                    mma16816(acc[mi][ni], ah, bh[ni]);
                    mma16816(acc[mi][ni], ah, bl[ni]);
                    mma16816(acc[mi][ni], al, bh[ni]);
                }
            }
        }
    };

    const int chunks = K >> 5;
    issue(0, 0);
    CP_COMMIT();
    for (int c = 0; c < chunks; c++) {
        if (c + 1 < chunks) { issue((c + 1) << 5, (c + 1) & 1); CP_COMMIT(); }
        if (c + 1 < chunks) asm volatile("cp.async.wait_group 1;");
        else                asm volatile("cp.async.wait_group 0;");
        __syncthreads();
        mma_chunk(c & 1);
        __syncthreads();
    }

    // epilogue
    #pragma unroll
    for (int mi = 0; mi < 4; mi++) {
        #pragma unroll
        for (int ni = 0; ni < 4; ni++) {
            long n = bn0 + wn * 32 + ni * 8 + (lane & 3) * 2;
            #pragma unroll
            for (int half = 0; half < 2; half++) {
                long m = bm0 + wm * 64 + mi * 16 + (lane >> 2) + half * 8;
                float2 v;
                v.x = acc[mi][ni][half * 2 + 0] * alpha;
                v.y = acc[mi][ni][half * 2 + 1] * alpha;
                if (BIAS) {
                    float2 bb = *(const float2*)(bias + n);
                    v.x += bb.x; v.y += bb.y;
                }
                if (SWISH) {
                    v.x = v.x / (1.0f + __expf(-v.x));
                    v.y = v.y / (1.0f + __expf(-v.y));
                }
                if (RES) {
                    float2 rr2 = *(const float2*)(res + m * (long)ldc + n);
                    v.x += rr2.x; v.y += rr2.y;
                }
                const long o = coff + m * (long)ldc + n;
                if (SPLITOUT) {
                    uint32_t h, l;
                    split2(v.x, v.y, h, l);
                    *(uint32_t*)(Ch + o) = h;
                    *(uint32_t*)(Cl + o) = l;
                } else {
                    *(float2*)(Cf + o) = v;
                }
            }
        }
    }
}

// ---------------- host orchestration ----------------
extern "C" void kernel_launch(void* const* d_in, const int* in_sizes, int n_in,
                              void* d_out, int out_size) {
    const float* x     = (const float*)d_in[0];
    const float* ln1_g = (const float*)d_in[1];
    const float* ln1_b = (const float*)d_in[2];
    const float* Wqkv  = (const float*)d_in[3];
    const float* bqkv  = (const float*)d_in[4];
    const float* Wm    = (const float*)d_in[5];
    const float* bm    = (const float*)d_in[6];
    const float* ln2_g = (const float*)d_in[7];
    const float* ln2_b = (const float*)d_in[8];
    const float* W1    = (const float*)d_in[9];
    const float* b1    = (const float*)d_in[10];
    const float* W2    = (const float*)d_in[11];
    const float* b2    = (const float*)d_in[12];
    float* out = (float*)d_out;

    bf16 *xnh, *xnl, *wqh, *wql, *wmh, *wml, *w1h, *w1l, *w2h, *w2l;
    bf16 *qkh, *qkl, *vth, *vtl, *pph, *ppl, *aoh, *aol, *x2nh, *x2nl, *hhh, *hhl;
    float *S, *x2;
    cudaGetSymbolAddress((void**)&xnh,  g_xn_h);  cudaGetSymbolAddress((void**)&xnl,  g_xn_l);
    cudaGetSymbolAddress((void**)&wqh,  g_Wqkv_h);cudaGetSymbolAddress((void**)&wql,  g_Wqkv_l);
    cudaGetSymbolAddress((void**)&wmh,  g_Wm_h);  cudaGetSymbolAddress((void**)&wml,  g_Wm_l);
    cudaGetSymbolAddress((void**)&w1h,  g_W1_h);  cudaGetSymbolAddress((void**)&w1l,  g_W1_l);
    cudaGetSymbolAddress((void**)&w2h,  g_W2_h);  cudaGetSymbolAddress((void**)&w2l,  g_W2_l);
    cudaGetSymbolAddress((void**)&qkh,  g_qkv_h); cudaGetSymbolAddress((void**)&qkl,  g_qkv_l);
    cudaGetSymbolAddress((void**)&vth,  g_vT_h);  cudaGetSymbolAddress((void**)&vtl,  g_vT_l);
    cudaGetSymbolAddress((void**)&pph,  g_P_h);   cudaGetSymbolAddress((void**)&ppl,  g_P_l);
    cudaGetSymbolAddress((void**)&aoh,  g_ao_h);  cudaGetSymbolAddress((void**)&aol,  g_ao_l);
    cudaGetSymbolAddress((void**)&x2nh, g_x2n_h); cudaGetSymbolAddress((void**)&x2nl, g_x2n_l);
    cudaGetSymbolAddress((void**)&hhh,  g_h_h);   cudaGetSymbolAddress((void**)&hhl,  g_h_l);
    cudaGetSymbolAddress((void**)&S,    g_S);
    cudaGetSymbolAddress((void**)&x2,   g_x2);

    cudaFuncSetAttribute(bf_gemm<true,  false, false, true >, cudaFuncAttributeMaxDynamicSharedMemorySize, GSMEM_SZ);
    cudaFuncSetAttribute(bf_gemm<false, false, false, false>, cudaFuncAttributeMaxDynamicSharedMemorySize, GSMEM_SZ);
    cudaFuncSetAttribute(bf_gemm<false, false, false, true >, cudaFuncAttributeMaxDynamicSharedMemorySize, GSMEM_SZ);
    cudaFuncSetAttribute(bf_gemm<true,  true,  false, false>, cudaFuncAttributeMaxDynamicSharedMemorySize, GSMEM_SZ);
    cudaFuncSetAttribute(bf_gemm<true,  false, true,  true >, cudaFuncAttributeMaxDynamicSharedMemorySize, GSMEM_SZ);

    dim3 tb(32, 8);
    // weight split+transpose: in [R][C] -> out [C][R]
    splitT<<<dim3(QKVN/32, DIN/32),  tb>>>(Wqkv, wqh, wql, DIN, QKVN);
    splitT<<<dim3(DIN/32, (NH*DVH)/32), tb>>>(Wm, wmh, wml, NH*DVH, DIN);
    splitT<<<dim3(DEXP/32, DIN/32),  tb>>>(W1, w1h, w1l, DIN, DEXP);
    splitT<<<dim3(DIN/32, DEXP/32),  tb>>>(W2, w2h, w2l, DEXP, DIN);

    // 1) LN1 -> xn hi/lo
    ln_split<<<NTOK, 128>>>(x, ln1_g, ln1_b, xnh, xnl);

    // 2) qkv = xn @ Wqkv + bqkv -> hi/lo   (4096 x 5120, K=512)
    bf_gemm<true, false, false, true><<<dim3(QKVN/128, NTOK/128, 1), 256, GSMEM_SZ>>>(
        xnh, xnl, wqh, wql, nullptr, qkh, qkl, bqkv, nullptr,
        DIN, DIN, DIN, QKVN,
        0, 0, 0, 0, 0, 0, 1, 1.0f);

    // 2b) transpose V per head -> vT hi/lo
    vtrans<<<dim3(SEQ/32, DVH/32, NB*NH), tb>>>(qkh, qkl, vth, vtl);

    // 3) S = scale * Q @ K^T   (2048x2048, K=64) x16
    bf_gemm<false, false, false, false><<<dim3(SEQ/128, SEQ/128, NB*NH), 256, GSMEM_SZ>>>(
        qkh + QOFF, qkl + QOFF, qkh + KOFF, qkl + KOFF, S, nullptr, nullptr, nullptr, nullptr,
        DH, QKVN, QKVN, SEQ,
        (long)SEQ*QKVN, DH, (long)SEQ*QKVN, DH,
        (long)NH*SEQ*SEQ, (long)SEQ*SEQ, NH, 0.125f);

    // 4) softmax -> P hi/lo
    softmax_split<<<NB*NH*SEQ, 256>>>(S, pph, ppl);

    // 5) ao = P @ V   (2048 x 512, K=2048) x16 -> hi/lo
    bf_gemm<false, false, false, true><<<dim3(DVH/128, SEQ/128, NB*NH), 256, GSMEM_SZ>>>(
        pph, ppl, vth, vtl, nullptr, aoh, aol, nullptr, nullptr,
        SEQ, SEQ, SEQ, NH*DVH,
        (long)NH*SEQ*SEQ, (long)SEQ*SEQ,
        (long)NH*DVH*SEQ, (long)DVH*SEQ,
        (long)SEQ*NH*DVH, DVH, NH, 1.0f);

    // 6) x2 = ao @ Wm + bm + x   (4096 x 512, K=4096)
    bf_gemm<true, true, false, false><<<dim3(DIN/128, NTOK/128, 1), 256, GSMEM_SZ>>>(
        aoh, aol, wmh, wml, x2, nullptr, nullptr, bm, x,
        NH*DVH, NH*DVH, NH*DVH, DIN,
        0, 0, 0, 0, 0, 0, 1, 1.0f);

    // 7) LN2 -> x2n hi/lo
    ln_split<<<NTOK, 128>>>(x2, ln2_g, ln2_b, x2nh, x2nl);

    // 8) h = swish(x2n @ W1 + b1) -> hi/lo  (4096 x 2048, K=512)
    bf_gemm<true, false, true, true><<<dim3(DEXP/128, NTOK/128, 1), 256, GSMEM_SZ>>>(
        x2nh, x2nl, w1h, w1l, nullptr, hhh, hhl, b1, nullptr,
        DIN, DIN, DIN, DEXP,
        0, 0, 0, 0, 0, 0, 1, 1.0f);

    // 9) out = h @ W2 + b2 + x2   (4096 x 512, K=2048)
    bf_gemm<true, true, false, false><<<dim3(DIN/128, NTOK/128, 1), 256, GSMEM_SZ>>>(
        hhh, hhl, w2h, w2l, out, nullptr, nullptr, b2, x2,
        DEXP, DEXP, DEXP, DIN,
        0, 0, 0, 0, 0, 0, 1, 1.0f);
}

// round 5
// speedup vs baseline: 1.4370x; 1.4370x over previous
#include <cuda_runtime.h>
#include <cuda_bf16.h>
#include <cuda_fp16.h>
#include <cstdint>
#include <math.h>

// ---------------- problem constants ----------------
#define NB    2
#define SEQ   2048
#define NTOK  (NB*SEQ)          // 4096
#define DIN   512
#define NH    8
#define DH    64
#define QOFF  0
#define KOFF  512
#define VOFF  1024
#define QKVN  5120
#define DVH   512
#define DEXP  2048

typedef __nv_bfloat16 bf16;

// ---------------- scratch (device globals) ----------------
__device__ bf16  g_xn_h [NTOK * (long)DIN];
__device__ bf16  g_xn_l [NTOK * (long)DIN];
__device__ bf16  g_Wqkv_h[(long)QKVN * DIN];   // [N][K]
__device__ bf16  g_Wqkv_l[(long)QKVN * DIN];
__device__ bf16  g_Wm_h [(long)DIN * (NH*DVH)];
__device__ bf16  g_Wm_l [(long)DIN * (NH*DVH)];
__device__ bf16  g_W1_h [(long)DEXP * DIN];
__device__ bf16  g_W1_l [(long)DEXP * DIN];
__device__ bf16  g_W2_h [(long)DIN * DEXP];
__device__ bf16  g_W2_l [(long)DIN * DEXP];
__device__ __half g_qkvf[NTOK * (long)QKVN];    // fp16 qkv
__device__ __half g_vT  [(long)NB*NH*DVH*SEQ];  // fp16 V^T per head
__device__ float g_S    [(long)NB*NH*SEQ*SEQ];
__device__ __half g_Pf  [(long)NB*NH*SEQ*SEQ];  // fp16 softmax
__device__ bf16  g_ao_h [NTOK * (long)(NH*DVH)];
__device__ bf16  g_ao_l [NTOK * (long)(NH*DVH)];
__device__ float g_x2   [NTOK * (long)DIN];
__device__ bf16  g_x2n_h[NTOK * (long)DIN];
__device__ bf16  g_x2n_l[NTOK * (long)DIN];
__device__ bf16  g_h_h  [NTOK * (long)DEXP];
__device__ bf16  g_h_l  [NTOK * (long)DEXP];

// ---------------- helpers ----------------
__device__ __forceinline__ uint32_t smem_u32(const void* p) {
    uint32_t a;
    asm("{ .reg .u64 t; cvta.to.shared.u64 t, %1; cvt.u32.u64 %0, t; }" : "=r"(a) : "l"(p));
    return a;
}
__device__ __forceinline__ void ldx4(uint32_t* r, uint32_t a) {
    asm volatile("ldmatrix.sync.aligned.m8n8.x4.shared.b16 {%0,%1,%2,%3}, [%4];"
                 : "=r"(r[0]), "=r"(r[1]), "=r"(r[2]), "=r"(r[3]) : "r"(a));
}
template<bool F16>
__device__ __forceinline__ void mma_t(float* d, const uint32_t* a, const uint32_t* b) {
    if (F16)
        asm volatile("mma.sync.aligned.m16n8k16.row.col.f32.f16.f16.f32 "
                     "{%0,%1,%2,%3}, {%4,%5,%6,%7}, {%8,%9}, {%0,%1,%2,%3};"
                     : "+f"(d[0]), "+f"(d[1]), "+f"(d[2]), "+f"(d[3])
                     : "r"(a[0]), "r"(a[1]), "r"(a[2]), "r"(a[3]), "r"(b[0]), "r"(b[1]));
    else
        asm volatile("mma.sync.aligned.m16n8k16.row.col.f32.bf16.bf16.f32 "
                     "{%0,%1,%2,%3}, {%4,%5,%6,%7}, {%8,%9}, {%0,%1,%2,%3};"
                     : "+f"(d[0]), "+f"(d[1]), "+f"(d[2]), "+f"(d[3])
                     : "r"(a[0]), "r"(a[1]), "r"(a[2]), "r"(a[3]), "r"(b[0]), "r"(b[1]));
}
__device__ __forceinline__ void cpa16(uint32_t dst, const void* src) {
    asm volatile("cp.async.cg.shared.global [%0], [%1], 16;" :: "r"(dst), "l"(src));
}
#define CP_COMMIT() asm volatile("cp.async.commit_group;")

__device__ __forceinline__ void split2(float x, float y, uint32_t& h, uint32_t& l) {
    __nv_bfloat162 hb = __float22bfloat162_rn(make_float2(x, y));
    uint32_t u = *(uint32_t*)&hb;
    float h0 = __uint_as_float(u << 16);
    float h1 = __uint_as_float(u & 0xFFFF0000u);
    __nv_bfloat162 lb = __float22bfloat162_rn(make_float2(x - h0, y - h1));
    h = u;
    l = *(uint32_t*)&lb;
}
__device__ __forceinline__ void split4(float4 v, uint2& h, uint2& l) {
    split2(v.x, v.y, h.x, l.x);
    split2(v.z, v.w, h.y, l.y);
}

// ---------------- split+transpose weights: fp32 [R][C] -> hi/lo [C][R] ----
__global__ void splitT(const float* __restrict__ in, bf16* __restrict__ oh,
                       bf16* __restrict__ ol, int R, int C) {
    __shared__ float t[32][33];
    int c0 = blockIdx.x * 32, r0 = blockIdx.y * 32;
    int tx = threadIdx.x, ty = threadIdx.y;
    #pragma unroll
    for (int j = 0; j < 4; j++)
        t[ty + j*8][tx] = in[(long)(r0 + ty + j*8) * C + c0 + tx];
    __syncthreads();
    #pragma unroll
    for (int j = 0; j < 4; j++) {
        float v = t[tx][ty + j*8];
        bf16 h = __float2bfloat16_rn(v);
        long o = (long)(c0 + ty + j*8) * R + r0 + tx;
        oh[o] = h;
        ol[o] = __float2bfloat16_rn(v - __bfloat162float(h));
    }
}

// ---------------- V transpose (fp16): qkv V section -> [bh][dvh][seq] -----
__global__ void vtrans(const __half* __restrict__ q, __half* __restrict__ v) {
    __shared__ uint16_t t[32][33];
    int bh = blockIdx.z, b = bh >> 3, hd = bh & 7;
    int t0 = blockIdx.x * 32, c0 = blockIdx.y * 32;
    int tx = threadIdx.x, ty = threadIdx.y;
    const long inb = (long)b * SEQ * QKVN + VOFF + hd * DVH;
    #pragma unroll
    for (int j = 0; j < 4; j++)
        t[ty + j*8][tx] = ((const uint16_t*)q)[inb + (long)(t0 + ty + j*8) * QKVN + c0 + tx];
    __syncthreads();
    const long outb = (long)bh * DVH * SEQ;
    #pragma unroll
    for (int j = 0; j < 4; j++)
        ((uint16_t*)v)[outb + (long)(c0 + ty + j*8) * SEQ + t0 + tx] = t[tx][ty + j*8];
}

// ---------------- LayerNorm -> hi/lo bf16 ----------------
__global__ void ln_split(const float* __restrict__ x, const float* __restrict__ g,
                         const float* __restrict__ bta, bf16* __restrict__ oh,
                         bf16* __restrict__ ol) {
    __shared__ float red[2][4];
    long row = blockIdx.x;
    const float* xr = x + row * DIN;
    int t = threadIdx.x;
    float4 v = ((const float4*)xr)[t];
    float s  = v.x + v.y + v.z + v.w;
    float ss = v.x*v.x + v.y*v.y + v.z*v.z + v.w*v.w;
    #pragma unroll
    for (int off = 16; off > 0; off >>= 1) {
        s  += __shfl_down_sync(0xffffffffu, s,  off);
        ss += __shfl_down_sync(0xffffffffu, ss, off);
    }
    int warp = t >> 5, lane = t & 31;
    if (lane == 0) { red[0][warp] = s; red[1][warp] = ss; }
    __syncthreads();
    if (t == 0) {
        float S0 = red[0][0] + red[0][1] + red[0][2] + red[0][3];
        float S1 = red[1][0] + red[1][1] + red[1][2] + red[1][3];
        float mu  = S0 * (1.0f/DIN);
        float var = S1 * (1.0f/DIN) - mu*mu;
        red[0][0] = mu;
        red[1][0] = rsqrtf(var + 1e-5f);
    }
    __syncthreads();
    float mu = red[0][0], inv = red[1][0];
    float4 gg = ((const float4*)g)[t];
    float4 bb = ((const float4*)bta)[t];
    float4 r;
    r.x = (v.x - mu) * inv * gg.x + bb.x;
    r.y = (v.y - mu) * inv * gg.y + bb.y;
    r.z = (v.z - mu) * inv * gg.z + bb.z;
    r.w = (v.w - mu) * inv * gg.w + bb.w;
    uint2 h, l;
    split4(r, h, l);
    ((uint2*)(oh + row * DIN))[t] = h;
    ((uint2*)(ol + row * DIN))[t] = l;
}

// ---------------- softmax -> fp16 P ----------------
__global__ void softmax_f16(const float* __restrict__ S, __half* __restrict__ P) {
    __shared__ float red[8];
    long row = blockIdx.x;
    const float* r = S + row * (long)SEQ;
    int t = threadIdx.x;
    float4 a = ((const float4*)r)[t];
    float4 b = ((const float4*)r)[t + 256];
    float m = fmaxf(fmaxf(fmaxf(a.x,a.y),fmaxf(a.z,a.w)),
                    fmaxf(fmaxf(b.x,b.y),fmaxf(b.z,b.w)));
    #pragma unroll
    for (int off = 16; off > 0; off >>= 1)
        m = fmaxf(m, __shfl_xor_sync(0xffffffffu, m, off));
    int warp = t >> 5, lane = t & 31;
    if (lane == 0) red[warp] = m;
    __syncthreads();
    m = red[0];
    #pragma unroll
    for (int i = 1; i < 8; i++) m = fmaxf(m, red[i]);
    a.x = __expf(a.x - m); a.y = __expf(a.y - m); a.z = __expf(a.z - m); a.w = __expf(a.w - m);
    b.x = __expf(b.x - m); b.y = __expf(b.y - m); b.z = __expf(b.z - m); b.w = __expf(b.w - m);
    float s = a.x+a.y+a.z+a.w + b.x+b.y+b.z+b.w;
    #pragma unroll
    for (int off = 16; off > 0; off >>= 1)
        s += __shfl_xor_sync(0xffffffffu, s, off);
    __syncthreads();
    if (lane == 0) red[warp] = s;
    __syncthreads();
    s = red[0];
    #pragma unroll
    for (int i = 1; i < 8; i++) s += red[i];
    float inv = 1.0f / s;
    __half2* pr = (__half2*)(P + row * SEQ);
    pr[2*t+0]   = __floats2half2_rn(a.x * inv, a.y * inv);
    pr[2*t+1]   = __floats2half2_rn(a.z * inv, a.w * inv);
    pr[2*t+512] = __floats2half2_rn(b.x * inv, b.y * inv);
    pr[2*t+513] = __floats2half2_rn(b.z * inv, b.w * inv);
}

// ---------------- generic HMMA GEMM ----------------
// TERMS=3: bf16 hi/lo 3-term (fp32-class). TERMS=1: fp16 single-pass.
// OMODE: 0 = fp32 out, 1 = bf16 hi/lo out, 2 = fp16 out.
// CTA 128x128, 8 warps 2x4, warp 64x32, BK=32.
// NSTAGE=2 (TERMS=3): stage 40960 B. NSTAGE=3 (TERMS=1): stage 20480 B.
#define SMEM3 (2 * 40960)
#define SMEM1 (3 * 20480)

template<int TERMS, int NSTAGE, int OMODE, bool BIAS, bool RES, bool SWISH>
__global__ void __launch_bounds__(256, 2)
g_gemm(const bf16* __restrict__ Ah, const bf16* __restrict__ Al,
       const bf16* __restrict__ Bh, const bf16* __restrict__ Bl,
       float* __restrict__ Cf, bf16* __restrict__ Ch, bf16* __restrict__ Cl,
       const float* __restrict__ bias, const float* __restrict__ res,
       int K, int lda, int ldb, int ldc,
       long sA1, long sA2, long sB1, long sB2, long sC1, long sC2,
       int zdiv, float alpha)
{
    extern __shared__ char sm[];
    const uint32_t smb = smem_u32(sm);
    const int tid = threadIdx.x, wid = tid >> 5, lane = tid & 31;
    const int wm = wid & 1, wn = wid >> 1;
    constexpr int STG  = (TERMS == 3) ? 40960 : 20480;
    constexpr int BOFF = (TERMS == 3) ? 20480 : 10240;

    int z = blockIdx.z, z1 = z / zdiv, z2 = z - z1 * zdiv;
    Ah += z1 * sA1 + (long)z2 * sA2;
    Bh += z1 * sB1 + (long)z2 * sB2;
    if (TERMS == 3) { Al += z1 * sA1 + (long)z2 * sA2; Bl += z1 * sB1 + (long)z2 * sB2; }
    const long coff = z1 * sC1 + (long)z2 * sC2;
    const long bm0 = (long)blockIdx.y * 128;
    const long bn0 = (long)blockIdx.x * 128;

    const int rr = tid >> 1;
    const int pq = (tid & 1) << 4;

    auto issue = [&](int k0, int stg) {
        const uint32_t base = smb + stg * STG;
        const bf16* as = Ah + (bm0 + rr) * (long)lda + k0 + pq;
        uint32_t da = base + rr * 80 + pq * 2;
        cpa16(da, as); cpa16(da + 16, as + 8);
        const bf16* bs = Bh + (bn0 + rr) * (long)ldb + k0 + pq;
        uint32_t db = base + BOFF + rr * 80 + pq * 2;
        cpa16(db, bs); cpa16(db + 16, bs + 8);
        if (TERMS == 3) {
            const bf16* asl = Al + (bm0 + rr) * (long)lda + k0 + pq;
            cpa16(da + 10240, asl); cpa16(da + 10240 + 16, asl + 8);
            const bf16* bsl = Bl + (bn0 + rr) * (long)ldb + k0 + pq;
            cpa16(db + 10240, bsl); cpa16(db + 10240 + 16, bsl + 8);
        }
    };

    float acc[4][4][4];
    #pragma unroll
    for (int i = 0; i < 4; i++)
        #pragma unroll
        for (int j = 0; j < 4; j++)
            #pragma unroll
            for (int t = 0; t < 4; t++) acc[i][j][t] = 0.0f;

    auto mma_chunk = [&](int stg) {
        const uint32_t base = smb + stg * STG;
        #pragma unroll
        for (int ks = 0; ks < 2; ks++) {
            const int kk = ks * 16;
            uint32_t bh[4][2], bl[4][2];
            #pragma unroll
            for (int p = 0; p < 2; p++) {
                uint32_t bd = base + BOFF + (wn * 32 + p * 16 + (lane & 15)) * 80
                                   + (kk + (lane >> 4) * 8) * 2;
                uint32_t r[4];
                ldx4(r, bd);
                bh[2*p][0] = r[0]; bh[2*p][1] = r[2];
                bh[2*p+1][0] = r[1]; bh[2*p+1][1] = r[3];
                if (TERMS == 3) {
                    ldx4(r, bd + 10240);
                    bl[2*p][0] = r[0]; bl[2*p][1] = r[2];
                    bl[2*p+1][0] = r[1]; bl[2*p+1][1] = r[3];
                }
            }
            #pragma unroll
            for (int mi = 0; mi < 4; mi++) {
                uint32_t ah[4], al[4];
                uint32_t ad = base + (wm * 64 + mi * 16 + (lane & 15)) * 80
                                   + (kk + (lane >> 4) * 8) * 2;
                ldx4(ah, ad);
                if (TERMS == 3) ldx4(al, ad + 10240);
                #pragma unroll
                for (int ni = 0; ni < 4; ni++) {
                    if (TERMS == 3) {
                        mma_t<false>(acc[mi][ni], ah, bh[ni]);
                        mma_t<false>(acc[mi][ni], ah, bl[ni]);
                        mma_t<false>(acc[mi][ni], al, bh[ni]);
                    } else {
                        mma_t<true>(acc[mi][ni], ah, bh[ni]);
                    }
                }
            }
        }
    };

    const int chunks = K >> 5;
    if (NSTAGE == 2) {
        issue(0, 0);
        CP_COMMIT();
        for (int c = 0; c < chunks; c++) {
            if (c + 1 < chunks) { issue((c + 1) << 5, (c + 1) & 1); CP_COMMIT(); }
            if (c + 1 < chunks) asm volatile("cp.async.wait_group 1;");
            else                asm volatile("cp.async.wait_group 0;");
            __syncthreads();
            mma_chunk(c & 1);
            __syncthreads();
        }
    } else {
        issue(0, 0); CP_COMMIT();
        if (chunks > 1) { issue(32, 1); CP_COMMIT(); }
        int stg = 0, nstg = (chunks > 2) ? 2 : ((chunks > 1) ? ((2 >= 3) ? 0 : 2) : 1);
        // stg cycles 0,1,2,...; next issue stage = (c+2)%3
        for (int c = 0; c < chunks; c++) {
            if (c + 1 < chunks) asm volatile("cp.async.wait_group 1;");
            else                asm volatile("cp.async.wait_group 0;");
            __syncthreads();
            if (c + 2 < chunks) {
                int is = stg + 2; if (is >= 3) is -= 3;
                issue((c + 2) << 5, is);
                CP_COMMIT();
            }
            mma_chunk(stg);
            if (++stg == 3) stg = 0;
        }
    }

    // epilogue
    #pragma unroll
    for (int mi = 0; mi < 4; mi++) {
        #pragma unroll
        for (int ni = 0; ni < 4; ni++) {
            long n = bn0 + wn * 32 + ni * 8 + (lane & 3) * 2;
            #pragma unroll
            for (int half_ = 0; half_ < 2; half_++) {
                long m = bm0 + wm * 64 + mi * 16 + (lane >> 2) + half_ * 8;
                float2 v;
                v.x = acc[mi][ni][half_ * 2 + 0] * alpha;
                v.y = acc[mi][ni][half_ * 2 + 1] * alpha;
                if (BIAS) {
                    float2 bb = *(const float2*)(bias + n);
                    v.x += bb.x; v.y += bb.y;
                }
                if (SWISH) {
                    v.x = v.x / (1.0f + __expf(-v.x));
                    v.y = v.y / (1.0f + __expf(-v.y));
                }
                if (RES) {
                    float2 rr2 = *(const float2*)(res + m * (long)ldc + n);
                    v.x += rr2.x; v.y += rr2.y;
                }
                const long o = coff + m * (long)ldc + n;
                if (OMODE == 0) {
                    *(float2*)(Cf + o) = v;
                } else if (OMODE == 1) {
                    uint32_t h, l;
                    split2(v.x, v.y, h, l);
                    *(uint32_t*)(Ch + o) = h;
                    *(uint32_t*)(Cl + o) = l;
                } else {
                    *(__half2*)((__half*)Ch + o) = __floats2half2_rn(v.x, v.y);
                }
            }
        }
    }
}

// ---------------- host orchestration ----------------
extern "C" void kernel_launch(void* const* d_in, const int* in_sizes, int n_in,
                              void* d_out, int out_size) {
    const float* x     = (const float*)d_in[0];
    const float* ln1_g = (const float*)d_in[1];
    const float* ln1_b = (const float*)d_in[2];
    const float* Wqkv  = (const float*)d_in[3];
    const float* bqkv  = (const float*)d_in[4];
    const float* Wm    = (const float*)d_in[5];
    const float* bm    = (const float*)d_in[6];
    const float* ln2_g = (const float*)d_in[7];
    const float* ln2_b = (const float*)d_in[8];
    const float* W1    = (const float*)d_in[9];
    const float* b1    = (const float*)d_in[10];
    const float* W2    = (const float*)d_in[11];
    const float* b2    = (const float*)d_in[12];
    float* out = (float*)d_out;

    bf16 *xnh, *xnl, *wqh, *wql, *wmh, *wml, *w1h, *w1l, *w2h, *w2l;
    bf16 *aoh, *aol, *x2nh, *x2nl, *hhh, *hhl;
    __half *qkf, *vt, *pf;
    float *S, *x2;
    cudaGetSymbolAddress((void**)&xnh,  g_xn_h);  cudaGetSymbolAddress((void**)&xnl,  g_xn_l);
    cudaGetSymbolAddress((void**)&wqh,  g_Wqkv_h);cudaGetSymbolAddress((void**)&wql,  g_Wqkv_l);
    cudaGetSymbolAddress((void**)&wmh,  g_Wm_h);  cudaGetSymbolAddress((void**)&wml,  g_Wm_l);
    cudaGetSymbolAddress((void**)&w1h,  g_W1_h);  cudaGetSymbolAddress((void**)&w1l,  g_W1_l);
    cudaGetSymbolAddress((void**)&w2h,  g_W2_h);  cudaGetSymbolAddress((void**)&w2l,  g_W2_l);
    cudaGetSymbolAddress((void**)&qkf,  g_qkvf);
    cudaGetSymbolAddress((void**)&vt,   g_vT);
    cudaGetSymbolAddress((void**)&pf,   g_Pf);
    cudaGetSymbolAddress((void**)&aoh,  g_ao_h);  cudaGetSymbolAddress((void**)&aol,  g_ao_l);
    cudaGetSymbolAddress((void**)&x2nh, g_x2n_h); cudaGetSymbolAddress((void**)&x2nl, g_x2n_l);
    cudaGetSymbolAddress((void**)&hhh,  g_h_h);   cudaGetSymbolAddress((void**)&hhl,  g_h_l);
    cudaGetSymbolAddress((void**)&S,    g_S);
    cudaGetSymbolAddress((void**)&x2,   g_x2);

    cudaFuncSetAttribute(g_gemm<3,2,2,true,false,false>, cudaFuncAttributeMaxDynamicSharedMemorySize, SMEM3);
    cudaFuncSetAttribute(g_gemm<1,3,0,false,false,false>, cudaFuncAttributeMaxDynamicSharedMemorySize, SMEM1);
    cudaFuncSetAttribute(g_gemm<1,3,1,false,false,false>, cudaFuncAttributeMaxDynamicSharedMemorySize, SMEM1);
    cudaFuncSetAttribute(g_gemm<3,2,0,true,true,false>,  cudaFuncAttributeMaxDynamicSharedMemorySize, SMEM3);
    cudaFuncSetAttribute(g_gemm<3,2,1,true,false,true>,  cudaFuncAttributeMaxDynamicSharedMemorySize, SMEM3);

    dim3 tb(32, 8);
    splitT<<<dim3(QKVN/32, DIN/32),  tb>>>(Wqkv, wqh, wql, DIN, QKVN);
    splitT<<<dim3(DIN/32, (NH*DVH)/32), tb>>>(Wm, wmh, wml, NH*DVH, DIN);
    splitT<<<dim3(DEXP/32, DIN/32),  tb>>>(W1, w1h, w1l, DIN, DEXP);
    splitT<<<dim3(DIN/32, DEXP/32),  tb>>>(W2, w2h, w2l, DEXP, DIN);

    // 1) LN1 -> xn hi/lo
    ln_split<<<NTOK, 128>>>(x, ln1_g, ln1_b, xnh, xnl);

    // 2) qkv = xn @ Wqkv + bqkv -> fp16   (4096 x 5120, K=512)
    g_gemm<3,2,2,true,false,false><<<dim3(QKVN/128, NTOK/128, 1), 256, SMEM3>>>(
        xnh, xnl, wqh, wql, nullptr, (bf16*)qkf, nullptr, bqkv, nullptr,
        DIN, DIN, DIN, QKVN,
        0, 0, 0, 0, 0, 0, 1, 1.0f);

    // 2b) V^T per head (fp16)
    vtrans<<<dim3(SEQ/32, DVH/32, NB*NH), tb>>>(qkf, vt);

    // 3) S = scale * Q @ K^T  fp16 single (2048x2048, K=64) x16
    g_gemm<1,3,0,false,false,false><<<dim3(SEQ/128, SEQ/128, NB*NH), 256, SMEM1>>>(
        (const bf16*)(qkf + QOFF), nullptr, (const bf16*)(qkf + KOFF), nullptr,
        S, nullptr, nullptr, nullptr, nullptr,
        DH, QKVN, QKVN, SEQ,
        (long)SEQ*QKVN, DH, (long)SEQ*QKVN, DH,
        (long)NH*SEQ*SEQ, (long)SEQ*SEQ, NH, 0.125f);

    // 4) softmax -> P fp16
    softmax_f16<<<NB*NH*SEQ, 256>>>(S, pf);

    // 5) ao = P @ V  fp16 single (2048 x 512, K=2048) x16 -> bf16 hi/lo
    g_gemm<1,3,1,false,false,false><<<dim3(DVH/128, SEQ/128, NB*NH), 256, SMEM1>>>(
        (const bf16*)pf, nullptr, (const bf16*)vt, nullptr,
        nullptr, aoh, aol, nullptr, nullptr,
        SEQ, SEQ, SEQ, NH*DVH,
        (long)NH*SEQ*SEQ, (long)SEQ*SEQ,
        (long)NH*DVH*SEQ, (long)DVH*SEQ,
        (long)SEQ*NH*DVH, DVH, NH, 1.0f);

    // 6) x2 = ao @ Wm + bm + x   (4096 x 512, K=4096)
    g_gemm<3,2,0,true,true,false><<<dim3(DIN/128, NTOK/128, 1), 256, SMEM3>>>(
        aoh, aol, wmh, wml, x2, nullptr, nullptr, bm, x,
        NH*DVH, NH*DVH, NH*DVH, DIN,
        0, 0, 0, 0, 0, 0, 1, 1.0f);

    // 7) LN2 -> x2n hi/lo
    ln_split<<<NTOK, 128>>>(x2, ln2_g, ln2_b, x2nh, x2nl);

    // 8) h = swish(x2n @ W1 + b1) -> hi/lo  (4096 x 2048, K=512)
    g_gemm<3,2,1,true,false,true><<<dim3(DEXP/128, NTOK/128, 1), 256, SMEM3>>>(
        x2nh, x2nl, w1h, w1l, nullptr, hhh, hhl, b1, nullptr,
        DIN, DIN, DIN, DEXP,
        0, 0, 0, 0, 0, 0, 1, 1.0f);

    // 9) out = h @ W2 + b2 + x2   (4096 x 512, K=2048)
    g_gemm<3,2,0,true,true,false><<<dim3(DIN/128, NTOK/128, 1), 256, SMEM3>>>(
        hhh, hhl, w2h, w2l, out, nullptr, nullptr, b2, x2,
        DEXP, DEXP, DEXP, DIN,
        0, 0, 0, 0, 0, 0, 1, 1.0f);
}

// round 6
// speedup vs baseline: 1.4579x; 1.0145x over previous
#include <cuda_runtime.h>
#include <cuda_fp16.h>
#include <cstdint>
#include <math.h>

// ---------------- problem constants ----------------
#define NB    2
#define SEQ   2048
#define NTOK  (NB*SEQ)          // 4096
#define DIN   512
#define NH    8
#define DH    64
#define QOFF  0
#define KOFF  512
#define VOFF  1024
#define QKVN  5120
#define DVH   512
#define DEXP  2048

typedef __half half_t;

// ---------------- scratch (device globals) ----------------
__device__ half_t g_xnf [NTOK * (long)DIN];
__device__ half_t g_Wq  [(long)QKVN * DIN];     // [N][K]
__device__ half_t g_Wmw [(long)DIN * (NH*DVH)];
__device__ half_t g_W1w [(long)DEXP * DIN];
__device__ half_t g_W2w [(long)DIN * DEXP];
__device__ half_t g_qkvf[NTOK * (long)QKVN];
__device__ half_t g_vT  [(long)NB*NH*DVH*SEQ];
__device__ half_t g_Sf  [(long)NB*NH*SEQ*SEQ];
__device__ half_t g_Pf  [(long)NB*NH*SEQ*SEQ];
__device__ half_t g_aof [NTOK * (long)(NH*DVH)];
__device__ float  g_x2  [NTOK * (long)DIN];
__device__ half_t g_x2nf[NTOK * (long)DIN];
__device__ half_t g_hf  [NTOK * (long)DEXP];

// ---------------- helpers ----------------
__device__ __forceinline__ uint32_t smem_u32(const void* p) {
    uint32_t a;
    asm("{ .reg .u64 t; cvta.to.shared.u64 t, %1; cvt.u32.u64 %0, t; }" : "=r"(a) : "l"(p));
    return a;
}
__device__ __forceinline__ void ldx4(uint32_t* r, uint32_t a) {
    asm volatile("ldmatrix.sync.aligned.m8n8.x4.shared.b16 {%0,%1,%2,%3}, [%4];"
                 : "=r"(r[0]), "=r"(r[1]), "=r"(r[2]), "=r"(r[3]) : "r"(a));
}
__device__ __forceinline__ void mma_f16(float* d, const uint32_t* a, const uint32_t* b) {
    asm volatile("mma.sync.aligned.m16n8k16.row.col.f32.f16.f16.f32 "
                 "{%0,%1,%2,%3}, {%4,%5,%6,%7}, {%8,%9}, {%0,%1,%2,%3};"
                 : "+f"(d[0]), "+f"(d[1]), "+f"(d[2]), "+f"(d[3])
                 : "r"(a[0]), "r"(a[1]), "r"(a[2]), "r"(a[3]), "r"(b[0]), "r"(b[1]));
}
__device__ __forceinline__ void cpa16(uint32_t dst, const void* src) {
    asm volatile("cp.async.cg.shared.global [%0], [%1], 16;" :: "r"(dst), "l"(src));
}
#define CP_COMMIT() asm volatile("cp.async.commit_group;")

// ---------------- weight convert+transpose: fp32 [R][C] -> fp16 [C][R] ----
__global__ void convT(const float* __restrict__ in, half_t* __restrict__ o, int R, int C) {
    __shared__ float t[32][33];
    int c0 = blockIdx.x * 32, r0 = blockIdx.y * 32;
    int tx = threadIdx.x, ty = threadIdx.y;
    #pragma unroll
    for (int j = 0; j < 4; j++)
        t[ty + j*8][tx] = in[(long)(r0 + ty + j*8) * C + c0 + tx];
    __syncthreads();
    #pragma unroll
    for (int j = 0; j < 4; j++)
        o[(long)(c0 + ty + j*8) * R + r0 + tx] = __float2half_rn(t[tx][ty + j*8]);
}

// ---------------- V transpose (fp16): qkv V section -> [bh][dvh][seq] -----
__global__ void vtrans(const half_t* __restrict__ q, half_t* __restrict__ v) {
    __shared__ uint16_t t[32][33];
    int bh = blockIdx.z, b = bh >> 3, hd = bh & 7;
    int t0 = blockIdx.x * 32, c0 = blockIdx.y * 32;
    int tx = threadIdx.x, ty = threadIdx.y;
    const long inb = (long)b * SEQ * QKVN + VOFF + hd * DVH;
    #pragma unroll
    for (int j = 0; j < 4; j++)
        t[ty + j*8][tx] = ((const uint16_t*)q)[inb + (long)(t0 + ty + j*8) * QKVN + c0 + tx];
    __syncthreads();
    const long outb = (long)bh * DVH * SEQ;
    #pragma unroll
    for (int j = 0; j < 4; j++)
        ((uint16_t*)v)[outb + (long)(c0 + ty + j*8) * SEQ + t0 + tx] = t[tx][ty + j*8];
}

// ---------------- LayerNorm -> fp16 ----------------
__global__ void ln_f16(const float* __restrict__ x, const float* __restrict__ g,
                       const float* __restrict__ bta, half_t* __restrict__ o) {
    __shared__ float red[2][4];
    long row = blockIdx.x;
    const float* xr = x + row * DIN;
    int t = threadIdx.x;
    float4 v = ((const float4*)xr)[t];
    float s  = v.x + v.y + v.z + v.w;
    float ss = v.x*v.x + v.y*v.y + v.z*v.z + v.w*v.w;
    #pragma unroll
    for (int off = 16; off > 0; off >>= 1) {
        s  += __shfl_down_sync(0xffffffffu, s,  off);
        ss += __shfl_down_sync(0xffffffffu, ss, off);
    }
    int warp = t >> 5, lane = t & 31;
    if (lane == 0) { red[0][warp] = s; red[1][warp] = ss; }
    __syncthreads();
    if (t == 0) {
        float S0 = red[0][0] + red[0][1] + red[0][2] + red[0][3];
        float S1 = red[1][0] + red[1][1] + red[1][2] + red[1][3];
        float mu  = S0 * (1.0f/DIN);
        float var = S1 * (1.0f/DIN) - mu*mu;
        red[0][0] = mu;
        red[1][0] = rsqrtf(var + 1e-5f);
    }
    __syncthreads();
    float mu = red[0][0], inv = red[1][0];
    float4 gg = ((const float4*)g)[t];
    float4 bb = ((const float4*)bta)[t];
    __half2 h0 = __floats2half2_rn((v.x - mu) * inv * gg.x + bb.x,
                                   (v.y - mu) * inv * gg.y + bb.y);
    __half2 h1 = __floats2half2_rn((v.z - mu) * inv * gg.z + bb.z,
                                   (v.w - mu) * inv * gg.w + bb.w);
    __half2* orow = (__half2*)(o + row * DIN);
    orow[2*t]   = h0;
    orow[2*t+1] = h1;
}

// ---------------- softmax: fp16 S row -> fp16 P row ----------------
__global__ void softmax_f16(const half_t* __restrict__ S, half_t* __restrict__ P) {
    __shared__ float red[8];
    long row = blockIdx.x;
    const uint4* r = (const uint4*)(S + row * (long)SEQ);
    int t = threadIdx.x;
    uint4 pk = r[t];                       // 8 halves
    float f[8];
    {
        __half2 a = *(__half2*)&pk.x, b = *(__half2*)&pk.y,
                c = *(__half2*)&pk.z, d = *(__half2*)&pk.w;
        float2 fa = __half22float2(a), fb = __half22float2(b),
               fc = __half22float2(c), fd = __half22float2(d);
        f[0]=fa.x; f[1]=fa.y; f[2]=fb.x; f[3]=fb.y;
        f[4]=fc.x; f[5]=fc.y; f[6]=fd.x; f[7]=fd.y;
    }
    float m = f[0];
    #pragma unroll
    for (int i = 1; i < 8; i++) m = fmaxf(m, f[i]);
    #pragma unroll
    for (int off = 16; off > 0; off >>= 1)
        m = fmaxf(m, __shfl_xor_sync(0xffffffffu, m, off));
    int warp = t >> 5, lane = t & 31;
    if (lane == 0) red[warp] = m;
    __syncthreads();
    m = red[0];
    #pragma unroll
    for (int i = 1; i < 8; i++) m = fmaxf(m, red[i]);
    float s = 0.f;
    #pragma unroll
    for (int i = 0; i < 8; i++) { f[i] = __expf(f[i] - m); s += f[i]; }
    #pragma unroll
    for (int off = 16; off > 0; off >>= 1)
        s += __shfl_xor_sync(0xffffffffu, s, off);
    __syncthreads();
    if (lane == 0) red[warp] = s;
    __syncthreads();
    s = red[0];
    #pragma unroll
    for (int i = 1; i < 8; i++) s += red[i];
    float inv = 1.0f / s;
    uint4 ok;
    *(__half2*)&ok.x = __floats2half2_rn(f[0]*inv, f[1]*inv);
    *(__half2*)&ok.y = __floats2half2_rn(f[2]*inv, f[3]*inv);
    *(__half2*)&ok.z = __floats2half2_rn(f[4]*inv, f[5]*inv);
    *(__half2*)&ok.w = __floats2half2_rn(f[6]*inv, f[7]*inv);
    ((uint4*)(P + row * (long)SEQ))[t] = ok;
}

// ---------------- fp16 HMMA GEMM, 3-stage cp.async ----------------
// C[M,N] = alpha * A[M,K] @ B[N,K]^T  [+bias][+res][swish]
// OMODE: 0 = fp32 out, 2 = fp16 out. CTA 128x128, 8 warps 2x4, BK=32.
#define STG_B   20480
#define SMEM_G  (3 * STG_B)   // 61440

template<int OMODE, bool BIAS, bool RES, bool SWISH>
__global__ void __launch_bounds__(256, 2)
f_gemm(const half_t* __restrict__ A, const half_t* __restrict__ B,
       float* __restrict__ Cf, half_t* __restrict__ Ch,
       const float* __restrict__ bias, const float* __restrict__ res,
       int K, int lda, int ldb, int ldc,
       long sA, long sB, long sC, int zdiv, long sA2, long sB2, long sC2,
       float alpha)
{
    extern __shared__ char sm[];
    const uint32_t smb = smem_u32(sm);
    const int tid = threadIdx.x, wid = tid >> 5, lane = tid & 31;
    const int wm = wid & 1, wn = wid >> 1;

    int z = blockIdx.z, z1 = z / zdiv, z2 = z - z1 * zdiv;
    A += z1 * sA + (long)z2 * sA2;
    B += z1 * sB + (long)z2 * sB2;
    const long coff = z1 * sC + (long)z2 * sC2;
    const long bm0 = (long)blockIdx.y * 128;
    const long bn0 = (long)blockIdx.x * 128;

    const int rr = tid >> 1;
    const int pq = (tid & 1) << 4;

    auto issue = [&](int k0, int stg) {
        const uint32_t base = smb + stg * STG_B;
        const half_t* as = A + (bm0 + rr) * (long)lda + k0 + pq;
        uint32_t da = base + rr * 80 + pq * 2;
        cpa16(da, as); cpa16(da + 16, as + 8);
        const half_t* bs = B + (bn0 + rr) * (long)ldb + k0 + pq;
        uint32_t db = base + 10240 + rr * 80 + pq * 2;
        cpa16(db, bs); cpa16(db + 16, bs + 8);
    };

    float acc[4][4][4];
    #pragma unroll
    for (int i = 0; i < 4; i++)
        #pragma unroll
        for (int j = 0; j < 4; j++)
            #pragma unroll
            for (int t = 0; t < 4; t++) acc[i][j][t] = 0.0f;

    auto mma_chunk = [&](int stg) {
        const uint32_t base = smb + stg * STG_B;
        #pragma unroll
        for (int ks = 0; ks < 2; ks++) {
            const int kk = ks * 16;
            uint32_t bfr[4][2];
            #pragma unroll
            for (int p = 0; p < 2; p++) {
                uint32_t bd = base + 10240 + (wn * 32 + p * 16 + (lane & 15)) * 80
                                   + (kk + (lane >> 4) * 8) * 2;
                uint32_t r[4];
                ldx4(r, bd);
                bfr[2*p][0] = r[0]; bfr[2*p][1] = r[2];
                bfr[2*p+1][0] = r[1]; bfr[2*p+1][1] = r[3];
            }
            #pragma unroll
            for (int mi = 0; mi < 4; mi++) {
                uint32_t afr[4];
                uint32_t ad = base + (wm * 64 + mi * 16 + (lane & 15)) * 80
                                   + (kk + (lane >> 4) * 8) * 2;
                ldx4(afr, ad);
                #pragma unroll
                for (int ni = 0; ni < 4; ni++)
                    mma_f16(acc[mi][ni], afr, bfr[ni]);
            }
        }
    };

    const int chunks = K >> 5;
    issue(0, 0); CP_COMMIT();
    if (chunks > 1) { issue(32, 1); CP_COMMIT(); }
    int stg = 0;
    for (int c = 0; c < chunks; c++) {
        if (c + 1 < chunks) asm volatile("cp.async.wait_group 1;");
        else                asm volatile("cp.async.wait_group 0;");
        __syncthreads();
        if (c + 2 < chunks) {
            int is = stg + 2; if (is >= 3) is -= 3;
            issue((c + 2) << 5, is);
            CP_COMMIT();
        }
        mma_chunk(stg);
        if (++stg == 3) stg = 0;
    }

    // epilogue
    #pragma unroll
    for (int mi = 0; mi < 4; mi++) {
        #pragma unroll
        for (int ni = 0; ni < 4; ni++) {
            long n = bn0 + wn * 32 + ni * 8 + (lane & 3) * 2;
            #pragma unroll
            for (int hf = 0; hf < 2; hf++) {
                long m = bm0 + wm * 64 + mi * 16 + (lane >> 2) + hf * 8;
                float2 v;
                v.x = acc[mi][ni][hf * 2 + 0] * alpha;
                v.y = acc[mi][ni][hf * 2 + 1] * alpha;
                if (BIAS) {
                    float2 bb = *(const float2*)(bias + n);
                    v.x += bb.x; v.y += bb.y;
                }
                if (SWISH) {
                    v.x = v.x / (1.0f + __expf(-v.x));
                    v.y = v.y / (1.0f + __expf(-v.y));
                }
                if (RES) {
                    float2 rr2 = *(const float2*)(res + m * (long)ldc + n);
                    v.x += rr2.x; v.y += rr2.y;
                }
                const long o = coff + m * (long)ldc + n;
                if (OMODE == 0) *(float2*)(Cf + o) = v;
                else            *(__half2*)(Ch + o) = __floats2half2_rn(v.x, v.y);
            }
        }
    }
}

// ---------------- host orchestration ----------------
extern "C" void kernel_launch(void* const* d_in, const int* in_sizes, int n_in,
                              void* d_out, int out_size) {
    const float* x     = (const float*)d_in[0];
    const float* ln1_g = (const float*)d_in[1];
    const float* ln1_b = (const float*)d_in[2];
    const float* Wqkv  = (const float*)d_in[3];
    const float* bqkv  = (const float*)d_in[4];
    const float* Wm    = (const float*)d_in[5];
    const float* bm    = (const float*)d_in[6];
    const float* ln2_g = (const float*)d_in[7];
    const float* ln2_b = (const float*)d_in[8];
    const float* W1    = (const float*)d_in[9];
    const float* b1    = (const float*)d_in[10];
    const float* W2    = (const float*)d_in[11];
    const float* b2    = (const float*)d_in[12];
    float* out = (float*)d_out;

    half_t *xnf, *wq, *wm, *w1, *w2, *qkf, *vt, *sf, *pf, *aof, *x2nf, *hf;
    float *x2;
    cudaGetSymbolAddress((void**)&xnf,  g_xnf);
    cudaGetSymbolAddress((void**)&wq,   g_Wq);
    cudaGetSymbolAddress((void**)&wm,   g_Wmw);
    cudaGetSymbolAddress((void**)&w1,   g_W1w);
    cudaGetSymbolAddress((void**)&w2,   g_W2w);
    cudaGetSymbolAddress((void**)&qkf,  g_qkvf);
    cudaGetSymbolAddress((void**)&vt,   g_vT);
    cudaGetSymbolAddress((void**)&sf,   g_Sf);
    cudaGetSymbolAddress((void**)&pf,   g_Pf);
    cudaGetSymbolAddress((void**)&aof,  g_aof);
    cudaGetSymbolAddress((void**)&x2nf, g_x2nf);
    cudaGetSymbolAddress((void**)&hf,   g_hf);
    cudaGetSymbolAddress((void**)&x2,   g_x2);

    cudaFuncSetAttribute(f_gemm<2,true,false,false>,  cudaFuncAttributeMaxDynamicSharedMemorySize, SMEM_G);
    cudaFuncSetAttribute(f_gemm<2,false,false,false>, cudaFuncAttributeMaxDynamicSharedMemorySize, SMEM_G);
    cudaFuncSetAttribute(f_gemm<0,true,true,false>,   cudaFuncAttributeMaxDynamicSharedMemorySize, SMEM_G);
    cudaFuncSetAttribute(f_gemm<2,true,false,true>,   cudaFuncAttributeMaxDynamicSharedMemorySize, SMEM_G);

    dim3 tb(32, 8);
    convT<<<dim3(QKVN/32, DIN/32),  tb>>>(Wqkv, wq, DIN, QKVN);
    convT<<<dim3(DIN/32, (NH*DVH)/32), tb>>>(Wm, wm, NH*DVH, DIN);
    convT<<<dim3(DEXP/32, DIN/32),  tb>>>(W1, w1, DIN, DEXP);
    convT<<<dim3(DIN/32, DEXP/32),  tb>>>(W2, w2, DEXP, DIN);

    // 1) LN1 -> fp16
    ln_f16<<<NTOK, 128>>>(x, ln1_g, ln1_b, xnf);

    // 2) qkv = xn @ Wqkv + bqkv -> fp16   (4096 x 5120, K=512)
    f_gemm<2,true,false,false><<<dim3(QKVN/128, NTOK/128, 1), 256, SMEM_G>>>(
        xnf, wq, nullptr, qkf, bqkv, nullptr,
        DIN, DIN, DIN, QKVN,
        0, 0, 0, 1, 0, 0, 0, 1.0f);

    // 2b) V^T per head
    vtrans<<<dim3(SEQ/32, DVH/32, NB*NH), tb>>>(qkf, vt);

    // 3) S = scale * Q @ K^T -> fp16   (2048x2048, K=64) x16
    f_gemm<2,false,false,false><<<dim3(SEQ/128, SEQ/128, NB*NH), 256, SMEM_G>>>(
        qkf + QOFF, qkf + KOFF, nullptr, sf, nullptr, nullptr,
        DH, QKVN, QKVN, SEQ,
        (long)SEQ*QKVN, (long)SEQ*QKVN, (long)NH*SEQ*SEQ, NH,
        DH, DH, (long)SEQ*SEQ, 0.125f);

    // 4) softmax -> P fp16
    softmax_f16<<<NB*NH*SEQ, 256>>>(sf, pf);

    // 5) ao = P @ V -> fp16   (2048 x 512, K=2048) x16
    f_gemm<2,false,false,false><<<dim3(DVH/128, SEQ/128, NB*NH), 256, SMEM_G>>>(
        pf, vt, nullptr, aof, nullptr, nullptr,
        SEQ, SEQ, SEQ, NH*DVH,
        (long)NH*SEQ*SEQ, (long)NH*DVH*SEQ, (long)SEQ*NH*DVH, NH,
        (long)SEQ*SEQ, (long)DVH*SEQ, DVH, 1.0f);

    // 6) x2 = ao @ Wm + bm + x -> fp32   (4096 x 512, K=4096)
    f_gemm<0,true,true,false><<<dim3(DIN/128, NTOK/128, 1), 256, SMEM_G>>>(
        aof, wm, x2, nullptr, bm, x,
        NH*DVH, NH*DVH, NH*DVH, DIN,
        0, 0, 0, 1, 0, 0, 0, 1.0f);

    // 7) LN2 -> fp16
    ln_f16<<<NTOK, 128>>>(x2, ln2_g, ln2_b, x2nf);

    // 8) h = swish(x2n @ W1 + b1) -> fp16  (4096 x 2048, K=512)
    f_gemm<2,true,false,true><<<dim3(DEXP/128, NTOK/128, 1), 256, SMEM_G>>>(
        x2nf, w1, nullptr, hf, b1, nullptr,
        DIN, DIN, DIN, DEXP,
        0, 0, 0, 1, 0, 0, 0, 1.0f);

    // 9) out = h @ W2 + b2 + x2 -> fp32   (4096 x 512, K=2048)
    f_gemm<0,true,true,false><<<dim3(DIN/128, NTOK/128, 1), 256, SMEM_G>>>(
        hf, w2, out, nullptr, b2, x2,
        DEXP, DEXP, DEXP, DIN,
        0, 0, 0, 1, 0, 0, 0, 1.0f);
}

// round 7
// speedup vs baseline: 1.9854x; 1.3618x over previous
#include <cuda_runtime.h>
#include <cuda_fp16.h>
#include <cstdint>
#include <math.h>

// ---------------- problem constants ----------------
#define NB    2
#define SEQ   2048
#define NTOK  (NB*SEQ)          // 4096
#define DIN   512
#define NH    8
#define DH    64
#define QOFF  0
#define KOFF  512
#define VOFF  1024
#define QKVN  5120
#define DVH   512
#define DEXP  2048

typedef __half half_t;

// ---------------- scratch (device globals) ----------------
__device__ half_t g_xnf [NTOK * (long)DIN];
__device__ half_t g_Wq  [(long)QKVN * DIN];     // [N][K]
__device__ half_t g_Wmw [(long)DIN * (NH*DVH)];
__device__ half_t g_W1w [(long)DEXP * DIN];
__device__ half_t g_W2w [(long)DIN * DEXP];
__device__ half_t g_qkvf[NTOK * (long)QKVN];
__device__ half_t g_aof [NTOK * (long)(NH*DVH)];
__device__ float  g_x2  [NTOK * (long)DIN];
__device__ half_t g_x2nf[NTOK * (long)DIN];
__device__ half_t g_hf  [NTOK * (long)DEXP];

// ---------------- helpers ----------------
__device__ __forceinline__ uint32_t smem_u32(const void* p) {
    uint32_t a;
    asm("{ .reg .u64 t; cvta.to.shared.u64 t, %1; cvt.u32.u64 %0, t; }" : "=r"(a) : "l"(p));
    return a;
}
__device__ __forceinline__ void ldx4(uint32_t* r, uint32_t a) {
    asm volatile("ldmatrix.sync.aligned.m8n8.x4.shared.b16 {%0,%1,%2,%3}, [%4];"
                 : "=r"(r[0]), "=r"(r[1]), "=r"(r[2]), "=r"(r[3]) : "r"(a));
}
__device__ __forceinline__ void ldx4t(uint32_t* r, uint32_t a) {
    asm volatile("ldmatrix.sync.aligned.m8n8.x4.trans.shared.b16 {%0,%1,%2,%3}, [%4];"
                 : "=r"(r[0]), "=r"(r[1]), "=r"(r[2]), "=r"(r[3]) : "r"(a));
}
__device__ __forceinline__ void mma_f16(float* d, const uint32_t* a, const uint32_t* b) {
    asm volatile("mma.sync.aligned.m16n8k16.row.col.f32.f16.f16.f32 "
                 "{%0,%1,%2,%3}, {%4,%5,%6,%7}, {%8,%9}, {%0,%1,%2,%3};"
                 : "+f"(d[0]), "+f"(d[1]), "+f"(d[2]), "+f"(d[3])
                 : "r"(a[0]), "r"(a[1]), "r"(a[2]), "r"(a[3]), "r"(b[0]), "r"(b[1]));
}
__device__ __forceinline__ void cpa16(uint32_t dst, const void* src) {
    asm volatile("cp.async.cg.shared.global [%0], [%1], 16;" :: "r"(dst), "l"(src));
}
#define CP_COMMIT() asm volatile("cp.async.commit_group;")

// ---------------- weight convert+transpose: fp32 [R][C] -> fp16 [C][R] ----
__global__ void convT(const float* __restrict__ in, half_t* __restrict__ o, int R, int C) {
    __shared__ float t[32][33];
    int c0 = blockIdx.x * 32, r0 = blockIdx.y * 32;
    int tx = threadIdx.x, ty = threadIdx.y;
    #pragma unroll
    for (int j = 0; j < 4; j++)
        t[ty + j*8][tx] = in[(long)(r0 + ty + j*8) * C + c0 + tx];
    __syncthreads();
    #pragma unroll
    for (int j = 0; j < 4; j++)
        o[(long)(c0 + ty + j*8) * R + r0 + tx] = __float2half_rn(t[tx][ty + j*8]);
}

// ---------------- LayerNorm -> fp16 ----------------
__global__ void ln_f16(const float* __restrict__ x, const float* __restrict__ g,
                       const float* __restrict__ bta, half_t* __restrict__ o) {
    __shared__ float red[2][4];
    long row = blockIdx.x;
    const float* xr = x + row * DIN;
    int t = threadIdx.x;
    float4 v = ((const float4*)xr)[t];
    float s  = v.x + v.y + v.z + v.w;
    float ss = v.x*v.x + v.y*v.y + v.z*v.z + v.w*v.w;
    #pragma unroll
    for (int off = 16; off > 0; off >>= 1) {
        s  += __shfl_down_sync(0xffffffffu, s,  off);
        ss += __shfl_down_sync(0xffffffffu, ss, off);
    }
    int warp = t >> 5, lane = t & 31;
    if (lane == 0) { red[0][warp] = s; red[1][warp] = ss; }
    __syncthreads();
    if (t == 0) {
        float S0 = red[0][0] + red[0][1] + red[0][2] + red[0][3];
        float S1 = red[1][0] + red[1][1] + red[1][2] + red[1][3];
        float mu  = S0 * (1.0f/DIN);
        float var = S1 * (1.0f/DIN) - mu*mu;
        red[0][0] = mu;
        red[1][0] = rsqrtf(var + 1e-5f);
    }
    __syncthreads();
    float mu = red[0][0], inv = red[1][0];
    float4 gg = ((const float4*)g)[t];
    float4 bb = ((const float4*)bta)[t];
    __half2 h0 = __floats2half2_rn((v.x - mu) * inv * gg.x + bb.x,
                                   (v.y - mu) * inv * gg.y + bb.y);
    __half2 h1 = __floats2half2_rn((v.z - mu) * inv * gg.z + bb.z,
                                   (v.w - mu) * inv * gg.w + bb.w);
    __half2* orow = (__half2*)(o + row * DIN);
    orow[2*t]   = h0;
    orow[2*t+1] = h1;
}

// ---------------- fused flash attention ----------------
// grid (4 vgroups, 16 qtiles, 16 bh), 256 thr. CTA: 128 q x 128 vcols,
// key chunks of 128. Q/K smem stride 144B, V/P stride 272B (conflict-free).
#define FAQ_OFF  0
#define FAK_OFF  18432
#define FAV_OFF  (FAK_OFF + 2*18432)        // 55296
#define FAP_OFF  (FAV_OFF + 2*34816)        // 124928
#define FAR_OFF  (FAP_OFF + 34816)          // 159744
#define FA_SMEM  (FAR_OFF + 4096)           // 163840

__global__ void __launch_bounds__(256, 1)
flash_attn(const half_t* __restrict__ qkv, half_t* __restrict__ ao) {
    extern __shared__ char sm[];
    const uint32_t smb = smem_u32(sm);
    float* redf = (float*)(sm + FAR_OFF);
    const int tid = threadIdx.x, wid = tid >> 5, lane = tid & 31;
    const int wm = wid & 1, wn = wid >> 1;
    const int vg = blockIdx.x, qt = blockIdx.y, bh = blockIdx.z;
    const int b = bh >> 3, hd = bh & 7;

    const half_t* Qg = qkv + (long)b * SEQ * QKVN + QOFF + hd * DH;
    const half_t* Kg = qkv + (long)b * SEQ * QKVN + KOFF + hd * DH;
    const half_t* Vg = qkv + (long)b * SEQ * QKVN + VOFF + hd * DVH + vg * 128;

    const int lrr = tid >> 1;               // loader row 0..127

    // Q tile load (once)
    {
        const int c0 = (tid & 1) * 32;
        uint32_t dq = smb + FAQ_OFF + lrr * 144 + c0 * 2;
        const half_t* src = Qg + (long)(qt * 128 + lrr) * QKVN + c0;
        cpa16(dq, src); cpa16(dq + 16, src + 8);
        cpa16(dq + 32, src + 16); cpa16(dq + 48, src + 24);
    }
    auto loadK = [&](int kc, int buf) {
        const int c0 = (tid & 1) * 32;
        uint32_t d = smb + FAK_OFF + buf * 18432 + lrr * 144 + c0 * 2;
        const half_t* src = Kg + (long)(kc * 128 + lrr) * QKVN + c0;
        cpa16(d, src); cpa16(d + 16, src + 8);
        cpa16(d + 32, src + 16); cpa16(d + 48, src + 24);
    };
    auto loadV = [&](int kc, int buf) {
        const int c0 = (tid & 1) * 64;
        uint32_t d = smb + FAV_OFF + buf * 34816 + lrr * 272 + c0 * 2;
        const half_t* src = Vg + (long)(kc * 128 + lrr) * QKVN + c0;
        #pragma unroll
        for (int i = 0; i < 8; i++) cpa16(d + i * 16, src + i * 8);
    };

    loadK(0, 0); loadV(0, 0); CP_COMMIT();

    float accO[4][4][4];
    float mrow[4][2], lrow[4][2];
    #pragma unroll
    for (int i = 0; i < 4; i++) {
        #pragma unroll
        for (int j = 0; j < 4; j++)
            #pragma unroll
            for (int t = 0; t < 4; t++) accO[i][j][t] = 0.0f;
        mrow[i][0] = mrow[i][1] = -1e30f;
        lrow[i][0] = lrow[i][1] = 0.0f;
    }

    for (int kc = 0; kc < 16; kc++) {
        const int buf = kc & 1;
        asm volatile("cp.async.wait_group 0;");
        __syncthreads();
        if (kc + 1 < 16) { loadK(kc + 1, buf ^ 1); loadV(kc + 1, buf ^ 1); CP_COMMIT(); }

        // ---- S = Q @ K_chunk^T (64x32 per warp) ----
        float accS[4][4][4];
        #pragma unroll
        for (int i = 0; i < 4; i++)
            #pragma unroll
            for (int j = 0; j < 4; j++)
                #pragma unroll
                for (int t = 0; t < 4; t++) accS[i][j][t] = 0.0f;
        const uint32_t kb = smb + FAK_OFF + buf * 18432;
        #pragma unroll
        for (int ks = 0; ks < 4; ks++) {
            const int kk = ks * 16;
            uint32_t bfr[4][2];
            #pragma unroll
            for (int p = 0; p < 2; p++) {
                uint32_t bd = kb + (wn * 32 + p * 16 + (lane & 15)) * 144
                                 + (kk + (lane >> 4) * 8) * 2;
                uint32_t r[4];
                ldx4(r, bd);
                bfr[2*p][0] = r[0]; bfr[2*p][1] = r[2];
                bfr[2*p+1][0] = r[1]; bfr[2*p+1][1] = r[3];
            }
            #pragma unroll
            for (int mi = 0; mi < 4; mi++) {
                uint32_t afr[4];
                uint32_t ad = smb + FAQ_OFF + (wm * 64 + mi * 16 + (lane & 15)) * 144
                                 + (kk + (lane >> 4) * 8) * 2;
                ldx4(afr, ad);
                #pragma unroll
                for (int ni = 0; ni < 4; ni++)
                    mma_f16(accS[mi][ni], afr, bfr[ni]);
            }
        }

        // ---- online softmax ----
        // per-thread row max over its 8 cols, then lane&3 group, then cross-warp
        #pragma unroll
        for (int mi = 0; mi < 4; mi++) {
            #pragma unroll
            for (int h2 = 0; h2 < 2; h2++) {
                float v = -1e30f;
                #pragma unroll
                for (int ni = 0; ni < 4; ni++)
                    v = fmaxf(v, fmaxf(accS[mi][ni][h2*2], accS[mi][ni][h2*2+1]));
                v = fmaxf(v, __shfl_xor_sync(0xffffffffu, v, 1));
                v = fmaxf(v, __shfl_xor_sync(0xffffffffu, v, 2));
                if ((lane & 3) == 0) {
                    int r = wm * 64 + mi * 16 + (lane >> 2) + h2 * 8;
                    redf[wn * 128 + r] = v * 0.125f;
                }
            }
        }
        __syncthreads();
        float scl[4][2];
        #pragma unroll
        for (int mi = 0; mi < 4; mi++) {
            #pragma unroll
            for (int h2 = 0; h2 < 2; h2++) {
                int r = wm * 64 + mi * 16 + (lane >> 2) + h2 * 8;
                float cm = fmaxf(fmaxf(redf[r], redf[128 + r]),
                                 fmaxf(redf[256 + r], redf[384 + r]));
                float mn = fmaxf(mrow[mi][h2], cm);
                scl[mi][h2] = __expf(mrow[mi][h2] - mn);
                mrow[mi][h2] = mn;
            }
        }
        // p = exp(s*scale - m), store to P smem, accumulate row sums, rescale O
        float psum[4][2];
        #pragma unroll
        for (int mi = 0; mi < 4; mi++) { psum[mi][0] = 0.f; psum[mi][1] = 0.f; }
        #pragma unroll
        for (int mi = 0; mi < 4; mi++) {
            #pragma unroll
            for (int ni = 0; ni < 4; ni++) {
                #pragma unroll
                for (int h2 = 0; h2 < 2; h2++) {
                    float p0 = __expf(accS[mi][ni][h2*2]   * 0.125f - mrow[mi][h2]);
                    float p1 = __expf(accS[mi][ni][h2*2+1] * 0.125f - mrow[mi][h2]);
                    psum[mi][h2] += p0 + p1;
                    int r = wm * 64 + mi * 16 + (lane >> 2) + h2 * 8;
                    int c = wn * 32 + ni * 8 + (lane & 3) * 2;
                    *(__half2*)(sm + FAP_OFF + r * 272 + c * 2) = __floats2half2_rn(p0, p1);
                }
            }
        }
        #pragma unroll
        for (int mi = 0; mi < 4; mi++) {
            #pragma unroll
            for (int h2 = 0; h2 < 2; h2++) {
                float s4 = psum[mi][h2];
                s4 += __shfl_xor_sync(0xffffffffu, s4, 1);
                s4 += __shfl_xor_sync(0xffffffffu, s4, 2);
                if ((lane & 3) == 0) {
                    int r = wm * 64 + mi * 16 + (lane >> 2) + h2 * 8;
                    redf[512 + wn * 128 + r] = s4;
                }
                #pragma unroll
                for (int ni = 0; ni < 4; ni++) {
                    accO[mi][ni][h2*2]   *= scl[mi][h2];
                    accO[mi][ni][h2*2+1] *= scl[mi][h2];
                }
            }
        }
        __syncthreads();
        #pragma unroll
        for (int mi = 0; mi < 4; mi++) {
            #pragma unroll
            for (int h2 = 0; h2 < 2; h2++) {
                int r = wm * 64 + mi * 16 + (lane >> 2) + h2 * 8;
                float s4 = redf[512 + r] + redf[512 + 128 + r]
                         + redf[512 + 256 + r] + redf[512 + 384 + r];
                lrow[mi][h2] = lrow[mi][h2] * scl[mi][h2] + s4;
            }
        }

        // ---- O += P @ V_chunk (64x32 per warp, K=128) ----
        const uint32_t vb = smb + FAV_OFF + buf * 34816;
        #pragma unroll
        for (int ks = 0; ks < 8; ks++) {
            const int kk = ks * 16;
            uint32_t bfr[4][2];
            #pragma unroll
            for (int p = 0; p < 2; p++) {
                int row = kk + (lane & 7) + ((lane >> 3) & 1) * 8;
                int col = wn * 32 + p * 16 + (lane >> 4) * 8;
                uint32_t bd = vb + row * 272 + col * 2;
                uint32_t r[4];
                ldx4t(r, bd);
                bfr[2*p][0] = r[0]; bfr[2*p][1] = r[1];
                bfr[2*p+1][0] = r[2]; bfr[2*p+1][1] = r[3];
            }
            #pragma unroll
            for (int mi = 0; mi < 4; mi++) {
                uint32_t afr[4];
                uint32_t ad = smb + FAP_OFF + (wm * 64 + mi * 16 + (lane & 15)) * 272
                                 + (kk + (lane >> 4) * 8) * 2;
                ldx4(afr, ad);
                #pragma unroll
                for (int ni = 0; ni < 4; ni++)
                    mma_f16(accO[mi][ni], afr, bfr[ni]);
            }
        }
        __syncthreads();
    }

    // ---- epilogue: O / l -> ao ----
    #pragma unroll
    for (int mi = 0; mi < 4; mi++) {
        #pragma unroll
        for (int h2 = 0; h2 < 2; h2++) {
            float inv = 1.0f / lrow[mi][h2];
            long tok = (long)b * SEQ + qt * 128 + wm * 64 + mi * 16 + (lane >> 2) + h2 * 8;
            #pragma unroll
            for (int ni = 0; ni < 4; ni++) {
                int col = hd * DVH + vg * 128 + wn * 32 + ni * 8 + (lane & 3) * 2;
                *(__half2*)(ao + tok * (NH * DVH) + col) =
                    __floats2half2_rn(accO[mi][ni][h2*2] * inv, accO[mi][ni][h2*2+1] * inv);
            }
        }
    }
}

// ---------------- fp16 HMMA GEMM, 3-stage cp.async ----------------
#define STG_B   20480
#define SMEM_G  (3 * STG_B)   // 61440

template<int OMODE, bool BIAS, bool RES, bool SWISH>
__global__ void __launch_bounds__(256, 2)
f_gemm(const half_t* __restrict__ A, const half_t* __restrict__ B,
       float* __restrict__ Cf, half_t* __restrict__ Ch,
       const float* __restrict__ bias, const float* __restrict__ res,
       int K, int lda, int ldb, int ldc, float alpha)
{
    extern __shared__ char sm[];
    const uint32_t smb = smem_u32(sm);
    const int tid = threadIdx.x, wid = tid >> 5, lane = tid & 31;
    const int wm = wid & 1, wn = wid >> 1;
    const long bm0 = (long)blockIdx.y * 128;
    const long bn0 = (long)blockIdx.x * 128;

    const int rr = tid >> 1;
    const int pq = (tid & 1) << 4;

    auto issue = [&](int k0, int stg) {
        const uint32_t base = smb + stg * STG_B;
        const half_t* as = A + (bm0 + rr) * (long)lda + k0 + pq;
        uint32_t da = base + rr * 80 + pq * 2;
        cpa16(da, as); cpa16(da + 16, as + 8);
        const half_t* bs = B + (bn0 + rr) * (long)ldb + k0 + pq;
        uint32_t db = base + 10240 + rr * 80 + pq * 2;
        cpa16(db, bs); cpa16(db + 16, bs + 8);
    };

    float acc[4][4][4];
    #pragma unroll
    for (int i = 0; i < 4; i++)
        #pragma unroll
        for (int j = 0; j < 4; j++)
            #pragma unroll
            for (int t = 0; t < 4; t++) acc[i][j][t] = 0.0f;

    auto mma_chunk = [&](int stg) {
        const uint32_t base = smb + stg * STG_B;
        #pragma unroll
        for (int ks = 0; ks < 2; ks++) {
            const int kk = ks * 16;
            uint32_t bfr[4][2];
            #pragma unroll
            for (int p = 0; p < 2; p++) {
                uint32_t bd = base + 10240 + (wn * 32 + p * 16 + (lane & 15)) * 80
                                   + (kk + (lane >> 4) * 8) * 2;
                uint32_t r[4];
                ldx4(r, bd);
                bfr[2*p][0] = r[0]; bfr[2*p][1] = r[2];
                bfr[2*p+1][0] = r[1]; bfr[2*p+1][1] = r[3];
            }
            #pragma unroll
            for (int mi = 0; mi < 4; mi++) {
                uint32_t afr[4];
                uint32_t ad = base + (wm * 64 + mi * 16 + (lane & 15)) * 80
                                   + (kk + (lane >> 4) * 8) * 2;
                ldx4(afr, ad);
                #pragma unroll
                for (int ni = 0; ni < 4; ni++)
                    mma_f16(acc[mi][ni], afr, bfr[ni]);
            }
        }
    };

    const int chunks = K >> 5;
    issue(0, 0); CP_COMMIT();
    if (chunks > 1) { issue(32, 1); CP_COMMIT(); }
    int stg = 0;
    for (int c = 0; c < chunks; c++) {
        if (c + 1 < chunks) asm volatile("cp.async.wait_group 1;");
        else                asm volatile("cp.async.wait_group 0;");
        __syncthreads();
        if (c + 2 < chunks) {
            int is = stg + 2; if (is >= 3) is -= 3;
            issue((c + 2) << 5, is);
            CP_COMMIT();
        }
        mma_chunk(stg);
        if (++stg == 3) stg = 0;
    }

    #pragma unroll
    for (int mi = 0; mi < 4; mi++) {
        #pragma unroll
        for (int ni = 0; ni < 4; ni++) {
            long n = bn0 + wn * 32 + ni * 8 + (lane & 3) * 2;
            #pragma unroll
            for (int hf = 0; hf < 2; hf++) {
                long m = bm0 + wm * 64 + mi * 16 + (lane >> 2) + hf * 8;
                float2 v;
                v.x = acc[mi][ni][hf * 2 + 0] * alpha;
                v.y = acc[mi][ni][hf * 2 + 1] * alpha;
                if (BIAS) {
                    float2 bb = *(const float2*)(bias + n);
                    v.x += bb.x; v.y += bb.y;
                }
                if (SWISH) {
                    v.x = v.x / (1.0f + __expf(-v.x));
                    v.y = v.y / (1.0f + __expf(-v.y));
                }
                if (RES) {
                    float2 rr2 = *(const float2*)(res + m * (long)ldc + n);
                    v.x += rr2.x; v.y += rr2.y;
                }
                const long o = m * (long)ldc + n;
                if (OMODE == 0) *(float2*)(Cf + o) = v;
                else            *(__half2*)(Ch + o) = __floats2half2_rn(v.x, v.y);
            }
        }
    }
}

// ---------------- host orchestration ----------------
extern "C" void kernel_launch(void* const* d_in, const int* in_sizes, int n_in,
                              void* d_out, int out_size) {
    const float* x     = (const float*)d_in[0];
    const float* ln1_g = (const float*)d_in[1];
    const float* ln1_b = (const float*)d_in[2];
    const float* Wqkv  = (const float*)d_in[3];
    const float* bqkv  = (const float*)d_in[4];
    const float* Wm    = (const float*)d_in[5];
    const float* bm    = (const float*)d_in[6];
    const float* ln2_g = (const float*)d_in[7];
    const float* ln2_b = (const float*)d_in[8];
    const float* W1    = (const float*)d_in[9];
    const float* b1    = (const float*)d_in[10];
    const float* W2    = (const float*)d_in[11];
    const float* b2    = (const float*)d_in[12];
    float* out = (float*)d_out;

    half_t *xnf, *wq, *wm, *w1, *w2, *qkf, *aof, *x2nf, *hf;
    float *x2;
    cudaGetSymbolAddress((void**)&xnf,  g_xnf);
    cudaGetSymbolAddress((void**)&wq,   g_Wq);
    cudaGetSymbolAddress((void**)&wm,   g_Wmw);
    cudaGetSymbolAddress((void**)&w1,   g_W1w);
    cudaGetSymbolAddress((void**)&w2,   g_W2w);
    cudaGetSymbolAddress((void**)&qkf,  g_qkvf);
    cudaGetSymbolAddress((void**)&aof,  g_aof);
    cudaGetSymbolAddress((void**)&x2nf, g_x2nf);
    cudaGetSymbolAddress((void**)&hf,   g_hf);
    cudaGetSymbolAddress((void**)&x2,   g_x2);

    cudaFuncSetAttribute(f_gemm<2,true,false,false>,  cudaFuncAttributeMaxDynamicSharedMemorySize, SMEM_G);
    cudaFuncSetAttribute(f_gemm<0,true,true,false>,   cudaFuncAttributeMaxDynamicSharedMemorySize, SMEM_G);
    cudaFuncSetAttribute(f_gemm<2,true,false,true>,   cudaFuncAttributeMaxDynamicSharedMemorySize, SMEM_G);
    cudaFuncSetAttribute(flash_attn, cudaFuncAttributeMaxDynamicSharedMemorySize, FA_SMEM);

    dim3 tb(32, 8);
    convT<<<dim3(QKVN/32, DIN/32),  tb>>>(Wqkv, wq, DIN, QKVN);
    convT<<<dim3(DIN/32, (NH*DVH)/32), tb>>>(Wm, wm, NH*DVH, DIN);
    convT<<<dim3(DEXP/32, DIN/32),  tb>>>(W1, w1, DIN, DEXP);
    convT<<<dim3(DIN/32, DEXP/32),  tb>>>(W2, w2, DEXP, DIN);

    // 1) LN1 -> fp16
    ln_f16<<<NTOK, 128>>>(x, ln1_g, ln1_b, xnf);

    // 2) qkv = xn @ Wqkv + bqkv -> fp16   (4096 x 5120, K=512)
    f_gemm<2,true,false,false><<<dim3(QKVN/128, NTOK/128), 256, SMEM_G>>>(
        xnf, wq, nullptr, qkf, bqkv, nullptr, DIN, DIN, DIN, QKVN, 1.0f);

    // 3) fused attention -> ao fp16
    flash_attn<<<dim3(4, 16, 16), 256, FA_SMEM>>>(qkf, aof);

    // 4) x2 = ao @ Wm + bm + x -> fp32   (4096 x 512, K=4096)
    f_gemm<0,true,true,false><<<dim3(DIN/128, NTOK/128), 256, SMEM_G>>>(
        aof, wm, x2, nullptr, bm, x, NH*DVH, NH*DVH, NH*DVH, DIN, 1.0f);

    // 5) LN2 -> fp16
    ln_f16<<<NTOK, 128>>>(x2, ln2_g, ln2_b, x2nf);

    // 6) h = swish(x2n @ W1 + b1) -> fp16  (4096 x 2048, K=512)
    f_gemm<2,true,false,true><<<dim3(DEXP/128, NTOK/128), 256, SMEM_G>>>(
        x2nf, w1, nullptr, hf, b1, nullptr, DIN, DIN, DIN, DEXP, 1.0f);

    // 7) out = h @ W2 + b2 + x2 -> fp32   (4096 x 512, K=2048)
    f_gemm<0,true,true,false><<<dim3(DIN/128, NTOK/128), 256, SMEM_G>>>(
        hf, w2, out, nullptr, b2, x2, DEXP, DEXP, DEXP, DIN, 1.0f);
}

// round 8
// speedup vs baseline: 2.0228x; 1.0188x over previous
#include <cuda_runtime.h>
#include <cuda_fp16.h>
#include <cstdint>
#include <math.h>

// ---------------- problem constants ----------------
#define NB    2
#define SEQ   2048
#define NTOK  (NB*SEQ)          // 4096
#define DIN   512
#define NH    8
#define DH    64
#define QOFF  0
#define KOFF  512
#define VOFF  1024
#define QKVN  5120
#define DVH   512
#define DEXP  2048

typedef __half half_t;

// ---------------- scratch (device globals) ----------------
__device__ half_t g_xnf [NTOK * (long)DIN];
__device__ half_t g_Wq  [(long)QKVN * DIN];     // [N][K]
__device__ half_t g_Wmw [(long)DIN * (NH*DVH)];
__device__ half_t g_W1w [(long)DEXP * DIN];
__device__ half_t g_W2w [(long)DIN * DEXP];
__device__ half_t g_qkvf[NTOK * (long)QKVN];
__device__ half_t g_aof [NTOK * (long)(NH*DVH)];
__device__ float  g_x2  [NTOK * (long)DIN];
__device__ half_t g_x2nf[NTOK * (long)DIN];
__device__ half_t g_hf  [NTOK * (long)DEXP];
__device__ float  g_part[4 * (long)NTOK * DIN];  // split-K partials (32 MB)

// ---------------- helpers ----------------
__device__ __forceinline__ uint32_t smem_u32(const void* p) {
    uint32_t a;
    asm("{ .reg .u64 t; cvta.to.shared.u64 t, %1; cvt.u32.u64 %0, t; }" : "=r"(a) : "l"(p));
    return a;
}
__device__ __forceinline__ void ldx4(uint32_t* r, uint32_t a) {
    asm volatile("ldmatrix.sync.aligned.m8n8.x4.shared.b16 {%0,%1,%2,%3}, [%4];"
                 : "=r"(r[0]), "=r"(r[1]), "=r"(r[2]), "=r"(r[3]) : "r"(a));
}
__device__ __forceinline__ void ldx4t(uint32_t* r, uint32_t a) {
    asm volatile("ldmatrix.sync.aligned.m8n8.x4.trans.shared.b16 {%0,%1,%2,%3}, [%4];"
                 : "=r"(r[0]), "=r"(r[1]), "=r"(r[2]), "=r"(r[3]) : "r"(a));
}
__device__ __forceinline__ void mma_f16(float* d, const uint32_t* a, const uint32_t* b) {
    asm volatile("mma.sync.aligned.m16n8k16.row.col.f32.f16.f16.f32 "
                 "{%0,%1,%2,%3}, {%4,%5,%6,%7}, {%8,%9}, {%0,%1,%2,%3};"
                 : "+f"(d[0]), "+f"(d[1]), "+f"(d[2]), "+f"(d[3])
                 : "r"(a[0]), "r"(a[1]), "r"(a[2]), "r"(a[3]), "r"(b[0]), "r"(b[1]));
}
__device__ __forceinline__ void cpa16(uint32_t dst, const void* src) {
    asm volatile("cp.async.cg.shared.global [%0], [%1], 16;" :: "r"(dst), "l"(src));
}
#define CP_COMMIT() asm volatile("cp.async.commit_group;")

// ---------------- merged weight convert+transpose ----------------
// 4 weights, fp32 [R][C] -> fp16 [C][R]. 32x32 tiles, 1D grid.
#define T0 ((QKVN/32)*(DIN/32))        // 2560
#define T1 ((DIN/32)*((NH*DVH)/32))    // 2048
#define T2 ((DEXP/32)*(DIN/32))        // 1024
#define T3 ((DIN/32)*(DEXP/32))        // 1024

__global__ void convAll(const float* __restrict__ i0, const float* __restrict__ i1,
                        const float* __restrict__ i2, const float* __restrict__ i3,
                        half_t* __restrict__ o0, half_t* __restrict__ o1,
                        half_t* __restrict__ o2, half_t* __restrict__ o3) {
    __shared__ float t[32][33];
    int id = blockIdx.x;
    const float* in; half_t* o; int R, C, ntx, lid;
    if (id < T0)                { in = i0; o = o0; R = DIN;    C = QKVN; ntx = QKVN/32; lid = id; }
    else if (id < T0+T1)        { in = i1; o = o1; R = NH*DVH; C = DIN;  ntx = DIN/32;  lid = id - T0; }
    else if (id < T0+T1+T2)     { in = i2; o = o2; R = DIN;    C = DEXP; ntx = DEXP/32; lid = id - T0 - T1; }
    else                        { in = i3; o = o3; R = DEXP;   C = DIN;  ntx = DIN/32;  lid = id - T0 - T1 - T2; }
    int c0 = (lid % ntx) * 32, r0 = (lid / ntx) * 32;
    int tx = threadIdx.x, ty = threadIdx.y;
    #pragma unroll
    for (int j = 0; j < 4; j++)
        t[ty + j*8][tx] = in[(long)(r0 + ty + j*8) * C + c0 + tx];
    __syncthreads();
    #pragma unroll
    for (int j = 0; j < 4; j++)
        o[(long)(c0 + ty + j*8) * R + r0 + tx] = __float2half_rn(t[tx][ty + j*8]);
}

// ---------------- LayerNorm -> fp16 ----------------
__global__ void ln_f16(const float* __restrict__ x, const float* __restrict__ g,
                       const float* __restrict__ bta, half_t* __restrict__ o) {
    __shared__ float red[2][4];
    long row = blockIdx.x;
    const float* xr = x + row * DIN;
    int t = threadIdx.x;
    float4 v = ((const float4*)xr)[t];
    float s  = v.x + v.y + v.z + v.w;
    float ss = v.x*v.x + v.y*v.y + v.z*v.z + v.w*v.w;
    #pragma unroll
    for (int off = 16; off > 0; off >>= 1) {
        s  += __shfl_down_sync(0xffffffffu, s,  off);
        ss += __shfl_down_sync(0xffffffffu, ss, off);
    }
    int warp = t >> 5, lane = t & 31;
    if (lane == 0) { red[0][warp] = s; red[1][warp] = ss; }
    __syncthreads();
    if (t == 0) {
        float S0 = red[0][0] + red[0][1] + red[0][2] + red[0][3];
        float S1 = red[1][0] + red[1][1] + red[1][2] + red[1][3];
        float mu  = S0 * (1.0f/DIN);
        float var = S1 * (1.0f/DIN) - mu*mu;
        red[0][0] = mu;
        red[1][0] = rsqrtf(var + 1e-5f);
    }
    __syncthreads();
    float mu = red[0][0], inv = red[1][0];
    float4 gg = ((const float4*)g)[t];
    float4 bb = ((const float4*)bta)[t];
    __half2 h0 = __floats2half2_rn((v.x - mu) * inv * gg.x + bb.x,
                                   (v.y - mu) * inv * gg.y + bb.y);
    __half2 h1 = __floats2half2_rn((v.z - mu) * inv * gg.z + bb.z,
                                   (v.w - mu) * inv * gg.w + bb.w);
    __half2* orow = (__half2*)(o + row * DIN);
    orow[2*t]   = h0;
    orow[2*t+1] = h1;
}

// ---------------- LN2 fused with 4-way split-K reduction ----------------
// x2 = sum(part[0..3]) + bm + x;  x2n = LN(x2) in fp16; x2 kept fp32.
__global__ void ln2sum4(const float* __restrict__ part, const float* __restrict__ x,
                        const float* __restrict__ bm, const float* __restrict__ g,
                        const float* __restrict__ bta, float* __restrict__ x2,
                        half_t* __restrict__ o) {
    __shared__ float red[2][4];
    long row = blockIdx.x;
    int t = threadIdx.x;
    const long base = row * DIN;
    float4 v = ((const float4*)(part + base))[t];
    {
        float4 p1 = ((const float4*)(part + (long)NTOK*DIN + base))[t];
        float4 p2 = ((const float4*)(part + 2L*NTOK*DIN + base))[t];
        float4 p3 = ((const float4*)(part + 3L*NTOK*DIN + base))[t];
        v.x += p1.x + p2.x + p3.x; v.y += p1.y + p2.y + p3.y;
        v.z += p1.z + p2.z + p3.z; v.w += p1.w + p2.w + p3.w;
    }
    {
        float4 bmv = ((const float4*)bm)[t];
        float4 xv  = ((const float4*)(x + base))[t];
        v.x += bmv.x + xv.x; v.y += bmv.y + xv.y;
        v.z += bmv.z + xv.z; v.w += bmv.w + xv.w;
    }
    ((float4*)(x2 + base))[t] = v;
    float s  = v.x + v.y + v.z + v.w;
    float ss = v.x*v.x + v.y*v.y + v.z*v.z + v.w*v.w;
    #pragma unroll
    for (int off = 16; off > 0; off >>= 1) {
        s  += __shfl_down_sync(0xffffffffu, s,  off);
        ss += __shfl_down_sync(0xffffffffu, ss, off);
    }
    int warp = t >> 5, lane = t & 31;
    if (lane == 0) { red[0][warp] = s; red[1][warp] = ss; }
    __syncthreads();
    if (t == 0) {
        float S0 = red[0][0] + red[0][1] + red[0][2] + red[0][3];
        float S1 = red[1][0] + red[1][1] + red[1][2] + red[1][3];
        float mu  = S0 * (1.0f/DIN);
        float var = S1 * (1.0f/DIN) - mu*mu;
        red[0][0] = mu;
        red[1][0] = rsqrtf(var + 1e-5f);
    }
    __syncthreads();
    float mu = red[0][0], inv = red[1][0];
    float4 gg = ((const float4*)g)[t];
    float4 bb = ((const float4*)bta)[t];
    __half2 h0 = __floats2half2_rn((v.x - mu) * inv * gg.x + bb.x,
                                   (v.y - mu) * inv * gg.y + bb.y);
    __half2 h1 = __floats2half2_rn((v.z - mu) * inv * gg.z + bb.z,
                                   (v.w - mu) * inv * gg.w + bb.w);
    __half2* orow = (__half2*)(o + row * DIN);
    orow[2*t]   = h0;
    orow[2*t+1] = h1;
}

// ---------------- final add: out = p0 + p1 + b2 + x2 ----------------
__global__ void final_add(const float* __restrict__ part, const float* __restrict__ b2,
                          const float* __restrict__ x2, float* __restrict__ out) {
    long row = blockIdx.x;
    int t = threadIdx.x;
    const long base = row * DIN;
    float4 v  = ((const float4*)(part + base))[t];
    float4 p1 = ((const float4*)(part + (long)NTOK*DIN + base))[t];
    float4 bv = ((const float4*)b2)[t];
    float4 xv = ((const float4*)(x2 + base))[t];
    v.x += p1.x + bv.x + xv.x; v.y += p1.y + bv.y + xv.y;
    v.z += p1.z + bv.z + xv.z; v.w += p1.w + bv.w + xv.w;
    ((float4*)(out + base))[t] = v;
}

// ---------------- fused flash attention (unchanged from R7) ----------------
#define FAQ_OFF  0
#define FAK_OFF  18432
#define FAV_OFF  (FAK_OFF + 2*18432)        // 55296
#define FAP_OFF  (FAV_OFF + 2*34816)        // 124928
#define FAR_OFF  (FAP_OFF + 34816)          // 159744
#define FA_SMEM  (FAR_OFF + 4096)           // 163840

__global__ void __launch_bounds__(256, 1)
flash_attn(const half_t* __restrict__ qkv, half_t* __restrict__ ao) {
    extern __shared__ char sm[];
    const uint32_t smb = smem_u32(sm);
    float* redf = (float*)(sm + FAR_OFF);
    const int tid = threadIdx.x, wid = tid >> 5, lane = tid & 31;
    const int wm = wid & 1, wn = wid >> 1;
    const int vg = blockIdx.x, qt = blockIdx.y, bh = blockIdx.z;
    const int b = bh >> 3, hd = bh & 7;

    const half_t* Qg = qkv + (long)b * SEQ * QKVN + QOFF + hd * DH;
    const half_t* Kg = qkv + (long)b * SEQ * QKVN + KOFF + hd * DH;
    const half_t* Vg = qkv + (long)b * SEQ * QKVN + VOFF + hd * DVH + vg * 128;

    const int lrr = tid >> 1;

    {
        const int c0 = (tid & 1) * 32;
        uint32_t dq = smb + FAQ_OFF + lrr * 144 + c0 * 2;
        const half_t* src = Qg + (long)(qt * 128 + lrr) * QKVN + c0;
        cpa16(dq, src); cpa16(dq + 16, src + 8);
        cpa16(dq + 32, src + 16); cpa16(dq + 48, src + 24);
    }
    auto loadK = [&](int kc, int buf) {
        const int c0 = (tid & 1) * 32;
        uint32_t d = smb + FAK_OFF + buf * 18432 + lrr * 144 + c0 * 2;
        const half_t* src = Kg + (long)(kc * 128 + lrr) * QKVN + c0;
        cpa16(d, src); cpa16(d + 16, src + 8);
        cpa16(d + 32, src + 16); cpa16(d + 48, src + 24);
    };
    auto loadV = [&](int kc, int buf) {
        const int c0 = (tid & 1) * 64;
        uint32_t d = smb + FAV_OFF + buf * 34816 + lrr * 272 + c0 * 2;
        const half_t* src = Vg + (long)(kc * 128 + lrr) * QKVN + c0;
        #pragma unroll
        for (int i = 0; i < 8; i++) cpa16(d + i * 16, src + i * 8);
    };

    loadK(0, 0); loadV(0, 0); CP_COMMIT();

    float accO[4][4][4];
    float mrow[4][2], lrow[4][2];
    #pragma unroll
    for (int i = 0; i < 4; i++) {
        #pragma unroll
        for (int j = 0; j < 4; j++)
            #pragma unroll
            for (int t = 0; t < 4; t++) accO[i][j][t] = 0.0f;
        mrow[i][0] = mrow[i][1] = -1e30f;
        lrow[i][0] = lrow[i][1] = 0.0f;
    }

    for (int kc = 0; kc < 16; kc++) {
        const int buf = kc & 1;
        asm volatile("cp.async.wait_group 0;");
        __syncthreads();
        if (kc + 1 < 16) { loadK(kc + 1, buf ^ 1); loadV(kc + 1, buf ^ 1); CP_COMMIT(); }

        float accS[4][4][4];
        #pragma unroll
        for (int i = 0; i < 4; i++)
            #pragma unroll
            for (int j = 0; j < 4; j++)
                #pragma unroll
                for (int t = 0; t < 4; t++) accS[i][j][t] = 0.0f;
        const uint32_t kb = smb + FAK_OFF + buf * 18432;
        #pragma unroll
        for (int ks = 0; ks < 4; ks++) {
            const int kk = ks * 16;
            uint32_t bfr[4][2];
            #pragma unroll
            for (int p = 0; p < 2; p++) {
                uint32_t bd = kb + (wn * 32 + p * 16 + (lane & 15)) * 144
                                 + (kk + (lane >> 4) * 8) * 2;
                uint32_t r[4];
                ldx4(r, bd);
                bfr[2*p][0] = r[0]; bfr[2*p][1] = r[2];
                bfr[2*p+1][0] = r[1]; bfr[2*p+1][1] = r[3];
            }
            #pragma unroll
            for (int mi = 0; mi < 4; mi++) {
                uint32_t afr[4];
                uint32_t ad = smb + FAQ_OFF + (wm * 64 + mi * 16 + (lane & 15)) * 144
                                 + (kk + (lane >> 4) * 8) * 2;
                ldx4(afr, ad);
                #pragma unroll
                for (int ni = 0; ni < 4; ni++)
                    mma_f16(accS[mi][ni], afr, bfr[ni]);
            }
        }

        #pragma unroll
        for (int mi = 0; mi < 4; mi++) {
            #pragma unroll
            for (int h2 = 0; h2 < 2; h2++) {
                float v = -1e30f;
                #pragma unroll
                for (int ni = 0; ni < 4; ni++)
                    v = fmaxf(v, fmaxf(accS[mi][ni][h2*2], accS[mi][ni][h2*2+1]));
                v = fmaxf(v, __shfl_xor_sync(0xffffffffu, v, 1));
                v = fmaxf(v, __shfl_xor_sync(0xffffffffu, v, 2));
                if ((lane & 3) == 0) {
                    int r = wm * 64 + mi * 16 + (lane >> 2) + h2 * 8;
                    redf[wn * 128 + r] = v * 0.125f;
                }
            }
        }
        __syncthreads();
        float scl[4][2];
        #pragma unroll
        for (int mi = 0; mi < 4; mi++) {
            #pragma unroll
            for (int h2 = 0; h2 < 2; h2++) {
                int r = wm * 64 + mi * 16 + (lane >> 2) + h2 * 8;
                float cm = fmaxf(fmaxf(redf[r], redf[128 + r]),
                                 fmaxf(redf[256 + r], redf[384 + r]));
                float mn = fmaxf(mrow[mi][h2], cm);
                scl[mi][h2] = __expf(mrow[mi][h2] - mn);
                mrow[mi][h2] = mn;
            }
        }
        float psum[4][2];
        #pragma unroll
        for (int mi = 0; mi < 4; mi++) { psum[mi][0] = 0.f; psum[mi][1] = 0.f; }
        #pragma unroll
        for (int mi = 0; mi < 4; mi++) {
            #pragma unroll
            for (int ni = 0; ni < 4; ni++) {
                #pragma unroll
                for (int h2 = 0; h2 < 2; h2++) {
                    float p0 = __expf(accS[mi][ni][h2*2]   * 0.125f - mrow[mi][h2]);
                    float p1 = __expf(accS[mi][ni][h2*2+1] * 0.125f - mrow[mi][h2]);
                    psum[mi][h2] += p0 + p1;
                    int r = wm * 64 + mi * 16 + (lane >> 2) + h2 * 8;
                    int c = wn * 32 + ni * 8 + (lane & 3) * 2;
                    *(__half2*)(sm + FAP_OFF + r * 272 + c * 2) = __floats2half2_rn(p0, p1);
                }
            }
        }
        #pragma unroll
        for (int mi = 0; mi < 4; mi++) {
            #pragma unroll
            for (int h2 = 0; h2 < 2; h2++) {
                float s4 = psum[mi][h2];
                s4 += __shfl_xor_sync(0xffffffffu, s4, 1);
                s4 += __shfl_xor_sync(0xffffffffu, s4, 2);
                if ((lane & 3) == 0) {
                    int r = wm * 64 + mi * 16 + (lane >> 2) + h2 * 8;
                    redf[512 + wn * 128 + r] = s4;
                }
                #pragma unroll
                for (int ni = 0; ni < 4; ni++) {
                    accO[mi][ni][h2*2]   *= scl[mi][h2];
                    accO[mi][ni][h2*2+1] *= scl[mi][h2];
                }
            }
        }
        __syncthreads();
        #pragma unroll
        for (int mi = 0; mi < 4; mi++) {
            #pragma unroll
            for (int h2 = 0; h2 < 2; h2++) {
                int r = wm * 64 + mi * 16 + (lane >> 2) + h2 * 8;
                float s4 = redf[512 + r] + redf[512 + 128 + r]
                         + redf[512 + 256 + r] + redf[512 + 384 + r];
                lrow[mi][h2] = lrow[mi][h2] * scl[mi][h2] + s4;
            }
        }

        const uint32_t vb = smb + FAV_OFF + buf * 34816;
        #pragma unroll
        for (int ks = 0; ks < 8; ks++) {
            const int kk = ks * 16;
            uint32_t bfr[4][2];
            #pragma unroll
            for (int p = 0; p < 2; p++) {
                int row = kk + (lane & 7) + ((lane >> 3) & 1) * 8;
                int col = wn * 32 + p * 16 + (lane >> 4) * 8;
                uint32_t bd = vb + row * 272 + col * 2;
                uint32_t r[4];
                ldx4t(r, bd);
                bfr[2*p][0] = r[0]; bfr[2*p][1] = r[1];
                bfr[2*p+1][0] = r[2]; bfr[2*p+1][1] = r[3];
            }
            #pragma unroll
            for (int mi = 0; mi < 4; mi++) {
                uint32_t afr[4];
                uint32_t ad = smb + FAP_OFF + (wm * 64 + mi * 16 + (lane & 15)) * 272
                                 + (kk + (lane >> 4) * 8) * 2;
                ldx4(afr, ad);
                #pragma unroll
                for (int ni = 0; ni < 4; ni++)
                    mma_f16(accO[mi][ni], afr, bfr[ni]);
            }
        }
        __syncthreads();
    }

    #pragma unroll
    for (int mi = 0; mi < 4; mi++) {
        #pragma unroll
        for (int h2 = 0; h2 < 2; h2++) {
            float inv = 1.0f / lrow[mi][h2];
            long tok = (long)b * SEQ + qt * 128 + wm * 64 + mi * 16 + (lane >> 2) + h2 * 8;
            #pragma unroll
            for (int ni = 0; ni < 4; ni++) {
                int col = hd * DVH + vg * 128 + wn * 32 + ni * 8 + (lane & 3) * 2;
                *(__half2*)(ao + tok * (NH * DVH) + col) =
                    __floats2half2_rn(accO[mi][ni][h2*2] * inv, accO[mi][ni][h2*2+1] * inv);
            }
        }
    }
}

// ---------------- fp16 HMMA GEMM, 4-stage cp.async, optional split-K ------
#define STG_B   20480
#define SMEM_G  (4 * STG_B)   // 81920

template<int OMODE, bool BIAS, bool RES, bool SWISH, bool SPLITK>
__global__ void __launch_bounds__(256, 2)
f_gemm(const half_t* __restrict__ A, const half_t* __restrict__ B,
       float* __restrict__ Cf, half_t* __restrict__ Ch,
       const float* __restrict__ bias, const float* __restrict__ res,
       int K, int lda, int ldb, int ldc, float alpha)
{
    extern __shared__ char sm[];
    const uint32_t smb = smem_u32(sm);
    const int tid = threadIdx.x, wid = tid >> 5, lane = tid & 31;
    const int wm = wid & 1, wn = wid >> 1;
    const long bm0 = (long)blockIdx.y * 128;
    const long bn0 = (long)blockIdx.x * 128;
    long zoff = 0;
    if (SPLITK) {
        A += (long)blockIdx.z * K;
        B += (long)blockIdx.z * K;
        zoff = (long)blockIdx.z * ((long)gridDim.y * 128) * ldc;
    }

    const int rr = tid >> 1;
    const int pq = (tid & 1) << 4;

    auto issue = [&](int k0, int stg) {
        const uint32_t base = smb + stg * STG_B;
        const half_t* as = A + (bm0 + rr) * (long)lda + k0 + pq;
        uint32_t da = base + rr * 80 + pq * 2;
        cpa16(da, as); cpa16(da + 16, as + 8);
        const half_t* bs = B + (bn0 + rr) * (long)ldb + k0 + pq;
        uint32_t db = base + 10240 + rr * 80 + pq * 2;
        cpa16(db, bs); cpa16(db + 16, bs + 8);
    };

    float acc[4][4][4];
    #pragma unroll
    for (int i = 0; i < 4; i++)
        #pragma unroll
        for (int j = 0; j < 4; j++)
            #pragma unroll
            for (int t = 0; t < 4; t++) acc[i][j][t] = 0.0f;

    auto mma_chunk = [&](int stg) {
        const uint32_t base = smb + stg * STG_B;
        #pragma unroll
        for (int ks = 0; ks < 2; ks++) {
            const int kk = ks * 16;
            uint32_t bfr[4][2];
            #pragma unroll
            for (int p = 0; p < 2; p++) {
                uint32_t bd = base + 10240 + (wn * 32 + p * 16 + (lane & 15)) * 80
                                   + (kk + (lane >> 4) * 8) * 2;
                uint32_t r[4];
                ldx4(r, bd);
                bfr[2*p][0] = r[0]; bfr[2*p][1] = r[2];
                bfr[2*p+1][0] = r[1]; bfr[2*p+1][1] = r[3];
            }
            #pragma unroll
            for (int mi = 0; mi < 4; mi++) {
                uint32_t afr[4];
                uint32_t ad = base + (wm * 64 + mi * 16 + (lane & 15)) * 80
                                   + (kk + (lane >> 4) * 8) * 2;
                ldx4(afr, ad);
                #pragma unroll
                for (int ni = 0; ni < 4; ni++)
                    mma_f16(acc[mi][ni], afr, bfr[ni]);
            }
        }
    };

    const int chunks = K >> 5;           // >= 16 for all shapes here
    issue(0, 0); CP_COMMIT();
    issue(32, 1); CP_COMMIT();
    issue(64, 2); CP_COMMIT();
    for (int c = 0; c < chunks; c++) {
        const int rem = chunks - 1 - c;
        if (rem >= 2)      asm volatile("cp.async.wait_group 2;");
        else if (rem == 1) asm volatile("cp.async.wait_group 1;");
        else               asm volatile("cp.async.wait_group 0;");
        __syncthreads();
        if (c + 3 < chunks) { issue((c + 3) << 5, (c + 3) & 3); CP_COMMIT(); }
        mma_chunk(c & 3);
    }

    #pragma unroll
    for (int mi = 0; mi < 4; mi++) {
        #pragma unroll
        for (int ni = 0; ni < 4; ni++) {
            long n = bn0 + wn * 32 + ni * 8 + (lane & 3) * 2;
            #pragma unroll
            for (int hf = 0; hf < 2; hf++) {
                long m = bm0 + wm * 64 + mi * 16 + (lane >> 2) + hf * 8;
                float2 v;
                v.x = acc[mi][ni][hf * 2 + 0] * alpha;
                v.y = acc[mi][ni][hf * 2 + 1] * alpha;
                if (BIAS) {
                    float2 bb = *(const float2*)(bias + n);
                    v.x += bb.x; v.y += bb.y;
                }
                if (SWISH) {
                    v.x = v.x / (1.0f + __expf(-v.x));
                    v.y = v.y / (1.0f + __expf(-v.y));
                }
                if (RES) {
                    float2 rr2 = *(const float2*)(res + m * (long)ldc + n);
                    v.x += rr2.x; v.y += rr2.y;
                }
                const long o = zoff + m * (long)ldc + n;
                if (OMODE == 0) *(float2*)(Cf + o) = v;
                else            *(__half2*)(Ch + o) = __floats2half2_rn(v.x, v.y);
            }
        }
    }
}

// ---------------- host orchestration ----------------
extern "C" void kernel_launch(void* const* d_in, const int* in_sizes, int n_in,
                              void* d_out, int out_size) {
    const float* x     = (const float*)d_in[0];
    const float* ln1_g = (const float*)d_in[1];
    const float* ln1_b = (const float*)d_in[2];
    const float* Wqkv  = (const float*)d_in[3];
    const float* bqkv  = (const float*)d_in[4];
    const float* Wm    = (const float*)d_in[5];
    const float* bm    = (const float*)d_in[6];
    const float* ln2_g = (const float*)d_in[7];
    const float* ln2_b = (const float*)d_in[8];
    const float* W1    = (const float*)d_in[9];
    const float* b1    = (const float*)d_in[10];
    const float* W2    = (const float*)d_in[11];
    const float* b2    = (const float*)d_in[12];
    float* out = (float*)d_out;

    half_t *xnf, *wq, *wm, *w1, *w2, *qkf, *aof, *x2nf, *hf;
    float *x2, *part;
    cudaGetSymbolAddress((void**)&xnf,  g_xnf);
    cudaGetSymbolAddress((void**)&wq,   g_Wq);
    cudaGetSymbolAddress((void**)&wm,   g_Wmw);
    cudaGetSymbolAddress((void**)&w1,   g_W1w);
    cudaGetSymbolAddress((void**)&w2,   g_W2w);
    cudaGetSymbolAddress((void**)&qkf,  g_qkvf);
    cudaGetSymbolAddress((void**)&aof,  g_aof);
    cudaGetSymbolAddress((void**)&x2nf, g_x2nf);
    cudaGetSymbolAddress((void**)&hf,   g_hf);
    cudaGetSymbolAddress((void**)&x2,   g_x2);
    cudaGetSymbolAddress((void**)&part, g_part);

    cudaFuncSetAttribute(f_gemm<2,true,false,false,false>, cudaFuncAttributeMaxDynamicSharedMemorySize, SMEM_G);
    cudaFuncSetAttribute(f_gemm<0,false,false,false,true>, cudaFuncAttributeMaxDynamicSharedMemorySize, SMEM_G);
    cudaFuncSetAttribute(f_gemm<2,true,false,true,false>,  cudaFuncAttributeMaxDynamicSharedMemorySize, SMEM_G);
    cudaFuncSetAttribute(flash_attn, cudaFuncAttributeMaxDynamicSharedMemorySize, FA_SMEM);

    // 0) all weight converts in one launch
    convAll<<<T0+T1+T2+T3, dim3(32, 8)>>>(Wqkv, Wm, W1, W2, wq, wm, w1, w2);

    // 1) LN1 -> fp16
    ln_f16<<<NTOK, 128>>>(x, ln1_g, ln1_b, xnf);

    // 2) qkv = xn @ Wqkv + bqkv -> fp16   (4096 x 5120, K=512)
    f_gemm<2,true,false,false,false><<<dim3(QKVN/128, NTOK/128), 256, SMEM_G>>>(
        xnf, wq, nullptr, qkf, bqkv, nullptr, DIN, DIN, DIN, QKVN, 1.0f);

    // 3) fused attention -> ao fp16
    flash_attn<<<dim3(4, 16, 16), 256, FA_SMEM>>>(qkf, aof);

    // 4) Wm split-K x4 -> fp32 partials   (4096 x 512, K=4x1024)
    f_gemm<0,false,false,false,true><<<dim3(DIN/128, NTOK/128, 4), 256, SMEM_G>>>(
        aof, wm, part, nullptr, nullptr, nullptr, 1024, NH*DVH, NH*DVH, DIN, 1.0f);

    // 5) LN2 fused with partial reduction + residual -> x2 fp32, x2n fp16
    ln2sum4<<<NTOK, 128>>>(part, x, bm, ln2_g, ln2_b, x2, x2nf);

    // 6) h = swish(x2n @ W1 + b1) -> fp16  (4096 x 2048, K=512)
    f_gemm<2,true,false,true,false><<<dim3(DEXP/128, NTOK/128), 256, SMEM_G>>>(
        x2nf, w1, nullptr, hf, b1, nullptr, DIN, DIN, DIN, DEXP, 1.0f);

    // 7) W2 split-K x2 -> fp32 partials   (4096 x 512, K=2x1024)
    f_gemm<0,false,false,false,true><<<dim3(DIN/128, NTOK/128, 2), 256, SMEM_G>>>(
        hf, w2, part, nullptr, nullptr, nullptr, 1024, DEXP, DEXP, DIN, 1.0f);

    // 8) out = p0 + p1 + b2 + x2
    final_add<<<NTOK, 128>>>(part, b2, x2, out);
}

// round 9
// speedup vs baseline: 2.2322x; 1.1035x over previous
#include <cuda_runtime.h>
#include <cuda_fp16.h>
#include <cstdint>
#include <math.h>

// ---------------- problem constants ----------------
#define NB    2
#define SEQ   2048
#define NTOK  (NB*SEQ)          // 4096
#define DIN   512
#define NH    8
#define DH    64
#define QOFF  0
#define KOFF  512
#define VOFF  1024
#define QKVN  5120
#define DVH   512
#define DEXP  2048

typedef __half half_t;

// ---------------- scratch (device globals) ----------------
__device__ half_t g_xnf [NTOK * (long)DIN];
__device__ half_t g_Wq  [(long)QKVN * DIN];     // [N][K]
__device__ half_t g_Wmw [(long)DIN * (NH*DVH)];
__device__ half_t g_W1w [(long)DEXP * DIN];
__device__ half_t g_W2w [(long)DIN * DEXP];
__device__ half_t g_qkvf[NTOK * (long)QKVN];
__device__ half_t g_aof [NTOK * (long)(NH*DVH)];
__device__ float  g_x2  [NTOK * (long)DIN];
__device__ half_t g_x2nf[NTOK * (long)DIN];
__device__ half_t g_hf  [NTOK * (long)DEXP];
__device__ float  g_part[4 * (long)NTOK * DIN];  // split-K partials

// ---------------- helpers ----------------
__device__ __forceinline__ uint32_t smem_u32(const void* p) {
    uint32_t a;
    asm("{ .reg .u64 t; cvta.to.shared.u64 t, %1; cvt.u32.u64 %0, t; }" : "=r"(a) : "l"(p));
    return a;
}
__device__ __forceinline__ void ldx4(uint32_t* r, uint32_t a) {
    asm volatile("ldmatrix.sync.aligned.m8n8.x4.shared.b16 {%0,%1,%2,%3}, [%4];"
                 : "=r"(r[0]), "=r"(r[1]), "=r"(r[2]), "=r"(r[3]) : "r"(a));
}
__device__ __forceinline__ void ldx4t(uint32_t* r, uint32_t a) {
    asm volatile("ldmatrix.sync.aligned.m8n8.x4.trans.shared.b16 {%0,%1,%2,%3}, [%4];"
                 : "=r"(r[0]), "=r"(r[1]), "=r"(r[2]), "=r"(r[3]) : "r"(a));
}
__device__ __forceinline__ void mma_f16(float* d, const uint32_t* a, const uint32_t* b) {
    asm volatile("mma.sync.aligned.m16n8k16.row.col.f32.f16.f16.f32 "
                 "{%0,%1,%2,%3}, {%4,%5,%6,%7}, {%8,%9}, {%0,%1,%2,%3};"
                 : "+f"(d[0]), "+f"(d[1]), "+f"(d[2]), "+f"(d[3])
                 : "r"(a[0]), "r"(a[1]), "r"(a[2]), "r"(a[3]), "r"(b[0]), "r"(b[1]));
}
__device__ __forceinline__ void cpa16(uint32_t dst, const void* src) {
    asm volatile("cp.async.cg.shared.global [%0], [%1], 16;" :: "r"(dst), "l"(src));
}
#define CP_COMMIT() asm volatile("cp.async.commit_group;")

// ---------------- merged weight convert+transpose ----------------
#define T0 ((QKVN/32)*(DIN/32))
#define T1 ((DIN/32)*((NH*DVH)/32))
#define T2 ((DEXP/32)*(DIN/32))
#define T3 ((DIN/32)*(DEXP/32))

__global__ void convAll(const float* __restrict__ i0, const float* __restrict__ i1,
                        const float* __restrict__ i2, const float* __restrict__ i3,
                        half_t* __restrict__ o0, half_t* __restrict__ o1,
                        half_t* __restrict__ o2, half_t* __restrict__ o3) {
    __shared__ float t[32][33];
    int id = blockIdx.x;
    const float* in; half_t* o; int R, C, ntx, lid;
    if (id < T0)                { in = i0; o = o0; R = DIN;    C = QKVN; ntx = QKVN/32; lid = id; }
    else if (id < T0+T1)        { in = i1; o = o1; R = NH*DVH; C = DIN;  ntx = DIN/32;  lid = id - T0; }
    else if (id < T0+T1+T2)     { in = i2; o = o2; R = DIN;    C = DEXP; ntx = DEXP/32; lid = id - T0 - T1; }
    else                        { in = i3; o = o3; R = DEXP;   C = DIN;  ntx = DIN/32;  lid = id - T0 - T1 - T2; }
    int c0 = (lid % ntx) * 32, r0 = (lid / ntx) * 32;
    int tx = threadIdx.x, ty = threadIdx.y;
    #pragma unroll
    for (int j = 0; j < 4; j++)
        t[ty + j*8][tx] = in[(long)(r0 + ty + j*8) * C + c0 + tx];
    __syncthreads();
    #pragma unroll
    for (int j = 0; j < 4; j++)
        o[(long)(c0 + ty + j*8) * R + r0 + tx] = __float2half_rn(t[tx][ty + j*8]);
}

// ---------------- LayerNorm -> fp16 ----------------
__global__ void ln_f16(const float* __restrict__ x, const float* __restrict__ g,
                       const float* __restrict__ bta, half_t* __restrict__ o) {
    __shared__ float red[2][4];
    long row = blockIdx.x;
    const float* xr = x + row * DIN;
    int t = threadIdx.x;
    float4 v = ((const float4*)xr)[t];
    float s  = v.x + v.y + v.z + v.w;
    float ss = v.x*v.x + v.y*v.y + v.z*v.z + v.w*v.w;
    #pragma unroll
    for (int off = 16; off > 0; off >>= 1) {
        s  += __shfl_down_sync(0xffffffffu, s,  off);
        ss += __shfl_down_sync(0xffffffffu, ss, off);
    }
    int warp = t >> 5, lane = t & 31;
    if (lane == 0) { red[0][warp] = s; red[1][warp] = ss; }
    __syncthreads();
    if (t == 0) {
        float S0 = red[0][0] + red[0][1] + red[0][2] + red[0][3];
        float S1 = red[1][0] + red[1][1] + red[1][2] + red[1][3];
        float mu  = S0 * (1.0f/DIN);
        float var = S1 * (1.0f/DIN) - mu*mu;
        red[0][0] = mu;
        red[1][0] = rsqrtf(var + 1e-5f);
    }
    __syncthreads();
    float mu = red[0][0], inv = red[1][0];
    float4 gg = ((const float4*)g)[t];
    float4 bb = ((const float4*)bta)[t];
    __half2 h0 = __floats2half2_rn((v.x - mu) * inv * gg.x + bb.x,
                                   (v.y - mu) * inv * gg.y + bb.y);
    __half2 h1 = __floats2half2_rn((v.z - mu) * inv * gg.z + bb.z,
                                   (v.w - mu) * inv * gg.w + bb.w);
    __half2* orow = (__half2*)(o + row * DIN);
    orow[2*t]   = h0;
    orow[2*t+1] = h1;
}

// ---------------- LN2 fused with 4-way split-K reduction ----------------
__global__ void ln2sum4(const float* __restrict__ part, const float* __restrict__ x,
                        const float* __restrict__ bm, const float* __restrict__ g,
                        const float* __restrict__ bta, float* __restrict__ x2,
                        half_t* __restrict__ o) {
    __shared__ float red[2][4];
    long row = blockIdx.x;
    int t = threadIdx.x;
    const long base = row * DIN;
    float4 v = ((const float4*)(part + base))[t];
    {
        float4 p1 = ((const float4*)(part + (long)NTOK*DIN + base))[t];
        float4 p2 = ((const float4*)(part + 2L*NTOK*DIN + base))[t];
        float4 p3 = ((const float4*)(part + 3L*NTOK*DIN + base))[t];
        v.x += p1.x + p2.x + p3.x; v.y += p1.y + p2.y + p3.y;
        v.z += p1.z + p2.z + p3.z; v.w += p1.w + p2.w + p3.w;
    }
    {
        float4 bmv = ((const float4*)bm)[t];
        float4 xv  = ((const float4*)(x + base))[t];
        v.x += bmv.x + xv.x; v.y += bmv.y + xv.y;
        v.z += bmv.z + xv.z; v.w += bmv.w + xv.w;
    }
    ((float4*)(x2 + base))[t] = v;
    float s  = v.x + v.y + v.z + v.w;
    float ss = v.x*v.x + v.y*v.y + v.z*v.z + v.w*v.w;
    #pragma unroll
    for (int off = 16; off > 0; off >>= 1) {
        s  += __shfl_down_sync(0xffffffffu, s,  off);
        ss += __shfl_down_sync(0xffffffffu, ss, off);
    }
    int warp = t >> 5, lane = t & 31;
    if (lane == 0) { red[0][warp] = s; red[1][warp] = ss; }
    __syncthreads();
    if (t == 0) {
        float S0 = red[0][0] + red[0][1] + red[0][2] + red[0][3];
        float S1 = red[1][0] + red[1][1] + red[1][2] + red[1][3];
        float mu  = S0 * (1.0f/DIN);
        float var = S1 * (1.0f/DIN) - mu*mu;
        red[0][0] = mu;
        red[1][0] = rsqrtf(var + 1e-5f);
    }
    __syncthreads();
    float mu = red[0][0], inv = red[1][0];
    float4 gg = ((const float4*)g)[t];
    float4 bb = ((const float4*)bta)[t];
    __half2 h0 = __floats2half2_rn((v.x - mu) * inv * gg.x + bb.x,
                                   (v.y - mu) * inv * gg.y + bb.y);
    __half2 h1 = __floats2half2_rn((v.z - mu) * inv * gg.z + bb.z,
                                   (v.w - mu) * inv * gg.w + bb.w);
    __half2* orow = (__half2*)(o + row * DIN);
    orow[2*t]   = h0;
    orow[2*t+1] = h1;
}

// ---------------- final add: out = p0 + p1 + b2 + x2 ----------------
__global__ void final_add(const float* __restrict__ part, const float* __restrict__ b2,
                          const float* __restrict__ x2, float* __restrict__ out) {
    long row = blockIdx.x;
    int t = threadIdx.x;
    const long base = row * DIN;
    float4 v  = ((const float4*)(part + base))[t];
    float4 p1 = ((const float4*)(part + (long)NTOK*DIN + base))[t];
    float4 bv = ((const float4*)b2)[t];
    float4 xv = ((const float4*)(x2 + base))[t];
    v.x += p1.x + bv.x + xv.x; v.y += p1.y + bv.y + xv.y;
    v.z += p1.z + bv.z + xv.z; v.w += p1.w + bv.w + xv.w;
    ((float4*)(out + base))[t] = v;
}

// ---------------- fused flash attention, register-resident P ----------------
// grid (4 vgroups, 16 qtiles, 16 bh), 256 thr. Warp w owns q-rows w*16..w*16+15
// and the FULL 128 S-cols / 128 v-cols; softmax is warp-local, P stays in regs.
#define FQ_OFF   0
#define FK_OFF   18432                      // 2 x 18432
#define FV_OFF   (FK_OFF + 2*18432)         // 2 x 34816
#define FA_SMEM  (FV_OFF + 2*34816)         // 124928

__global__ void __launch_bounds__(256, 1)
flash_attn(const half_t* __restrict__ qkv, half_t* __restrict__ ao) {
    extern __shared__ char sm[];
    const uint32_t smb = smem_u32(sm);
    const int tid = threadIdx.x, wid = tid >> 5, lane = tid & 31;
    const int vg = blockIdx.x, qt = blockIdx.y, bh = blockIdx.z;
    const int b = bh >> 3, hd = bh & 7;

    const half_t* Qg = qkv + (long)b * SEQ * QKVN + QOFF + hd * DH;
    const half_t* Kg = qkv + (long)b * SEQ * QKVN + KOFF + hd * DH;
    const half_t* Vg = qkv + (long)b * SEQ * QKVN + VOFF + hd * DVH + vg * 128;

    const int lrr = tid >> 1;

    // Q tile (once)
    {
        const int c0 = (tid & 1) * 32;
        uint32_t dq = smb + FQ_OFF + lrr * 144 + c0 * 2;
        const half_t* src = Qg + (long)(qt * 128 + lrr) * QKVN + c0;
        cpa16(dq, src); cpa16(dq + 16, src + 8);
        cpa16(dq + 32, src + 16); cpa16(dq + 48, src + 24);
    }
    auto loadK = [&](int kc, int buf) {
        const int c0 = (tid & 1) * 32;
        uint32_t d = smb + FK_OFF + buf * 18432 + lrr * 144 + c0 * 2;
        const half_t* src = Kg + (long)(kc * 128 + lrr) * QKVN + c0;
        cpa16(d, src); cpa16(d + 16, src + 8);
        cpa16(d + 32, src + 16); cpa16(d + 48, src + 24);
    };
    auto loadV = [&](int kc, int buf) {
        const int c0 = (tid & 1) * 64;
        uint32_t d = smb + FV_OFF + buf * 34816 + lrr * 272 + c0 * 2;
        const half_t* src = Vg + (long)(kc * 128 + lrr) * QKVN + c0;
        #pragma unroll
        for (int i = 0; i < 8; i++) cpa16(d + i * 16, src + i * 8);
    };

    loadK(0, 0); loadV(0, 0); CP_COMMIT();

    float accO[16][4];
    float mrow0 = -1e30f, mrow1 = -1e30f, lrow0 = 0.f, lrow1 = 0.f;
    #pragma unroll
    for (int j = 0; j < 16; j++)
        #pragma unroll
        for (int t = 0; t < 4; t++) accO[j][t] = 0.0f;

    uint32_t qfrag[4][4];

    for (int kc = 0; kc < 16; kc++) {
        const int buf = kc & 1;
        asm volatile("cp.async.wait_group 0;");
        __syncthreads();
        if (kc == 0) {
            // hoist Q fragments (rows wid*16, k = DH)
            #pragma unroll
            for (int ks = 0; ks < 4; ks++) {
                uint32_t ad = smb + FQ_OFF + (wid * 16 + (lane & 15)) * 144
                                 + (ks * 16 + (lane >> 4) * 8) * 2;
                ldx4(qfrag[ks], ad);
            }
        }
        if (kc + 1 < 16) { loadK(kc + 1, buf ^ 1); loadV(kc + 1, buf ^ 1); CP_COMMIT(); }

        // ---- S = Q(16 rows) @ K_chunk^T (full 128 cols) ----
        float accS[16][4];
        #pragma unroll
        for (int j = 0; j < 16; j++)
            #pragma unroll
            for (int t = 0; t < 4; t++) accS[j][t] = 0.0f;
        const uint32_t kb = smb + FK_OFF + buf * 18432;
        #pragma unroll
        for (int ks = 0; ks < 4; ks++) {
            #pragma unroll
            for (int p = 0; p < 8; p++) {
                uint32_t r[4];
                ldx4(r, kb + (p * 16 + (lane & 15)) * 144 + (ks * 16 + (lane >> 4) * 8) * 2);
                uint32_t b0[2] = { r[0], r[2] };
                uint32_t b1[2] = { r[1], r[3] };
                mma_f16(accS[2*p],   qfrag[ks], b0);
                mma_f16(accS[2*p+1], qfrag[ks], b1);
            }
        }

        // ---- warp-local online softmax ----
        float m0 = -1e30f, m1 = -1e30f;
        #pragma unroll
        for (int j = 0; j < 16; j++) {
            m0 = fmaxf(m0, fmaxf(accS[j][0], accS[j][1]));
            m1 = fmaxf(m1, fmaxf(accS[j][2], accS[j][3]));
        }
        m0 = fmaxf(m0, __shfl_xor_sync(0xffffffffu, m0, 1));
        m0 = fmaxf(m0, __shfl_xor_sync(0xffffffffu, m0, 2));
        m1 = fmaxf(m1, __shfl_xor_sync(0xffffffffu, m1, 1));
        m1 = fmaxf(m1, __shfl_xor_sync(0xffffffffu, m1, 2));
        float nm0 = fmaxf(mrow0, m0 * 0.125f);
        float nm1 = fmaxf(mrow1, m1 * 0.125f);
        float scl0 = __expf(mrow0 - nm0);
        float scl1 = __expf(mrow1 - nm1);
        mrow0 = nm0; mrow1 = nm1;

        uint32_t pfrag[8][4];
        float ps0 = 0.f, ps1 = 0.f;
        #pragma unroll
        for (int j = 0; j < 16; j++) {
            float p0 = __expf(accS[j][0] * 0.125f - nm0);
            float p1 = __expf(accS[j][1] * 0.125f - nm0);
            float p2 = __expf(accS[j][2] * 0.125f - nm1);
            float p3 = __expf(accS[j][3] * 0.125f - nm1);
            ps0 += p0 + p1; ps1 += p2 + p3;
            uint32_t lo = __half2_raw(__floats2half2_rn(p0, p1)).x |
                          ((uint32_t)__half2_raw(__floats2half2_rn(p0, p1)).y << 16);
            // simpler: reinterpret
            __half2 hlo = __floats2half2_rn(p0, p1);
            __half2 hhi = __floats2half2_rn(p2, p3);
            if ((j & 1) == 0) {
                pfrag[j >> 1][0] = *(uint32_t*)&hlo;
                pfrag[j >> 1][1] = *(uint32_t*)&hhi;
            } else {
                pfrag[j >> 1][2] = *(uint32_t*)&hlo;
                pfrag[j >> 1][3] = *(uint32_t*)&hhi;
            }
            (void)lo;
        }
        ps0 += __shfl_xor_sync(0xffffffffu, ps0, 1);
        ps0 += __shfl_xor_sync(0xffffffffu, ps0, 2);
        ps1 += __shfl_xor_sync(0xffffffffu, ps1, 1);
        ps1 += __shfl_xor_sync(0xffffffffu, ps1, 2);
        lrow0 = lrow0 * scl0 + ps0;
        lrow1 = lrow1 * scl1 + ps1;
        #pragma unroll
        for (int j = 0; j < 16; j++) {
            accO[j][0] *= scl0; accO[j][1] *= scl0;
            accO[j][2] *= scl1; accO[j][3] *= scl1;
        }

        // ---- O += P(regs) @ V_chunk (full 128 vcols) ----
        const uint32_t vb = smb + FV_OFF + buf * 34816;
        #pragma unroll
        for (int ks = 0; ks < 8; ks++) {
            #pragma unroll
            for (int p = 0; p < 8; p++) {
                uint32_t r[4];
                ldx4t(r, vb + (ks * 16 + (lane & 7) + ((lane >> 3) & 1) * 8) * 272
                           + (p * 16 + (lane >> 4) * 8) * 2);
                uint32_t b0[2] = { r[0], r[1] };
                uint32_t b1[2] = { r[2], r[3] };
                mma_f16(accO[2*p],   pfrag[ks], b0);
                mma_f16(accO[2*p+1], pfrag[ks], b1);
            }
        }
        __syncthreads();
    }

    // ---- epilogue: O / l -> ao ----
    const float inv0 = 1.0f / lrow0;
    const float inv1 = 1.0f / lrow1;
    const long tok0 = (long)b * SEQ + qt * 128 + wid * 16 + (lane >> 2);
    #pragma unroll
    for (int j = 0; j < 16; j++) {
        int col = hd * DVH + vg * 128 + j * 8 + (lane & 3) * 2;
        *(__half2*)(ao + tok0 * (NH * DVH) + col) =
            __floats2half2_rn(accO[j][0] * inv0, accO[j][1] * inv0);
        *(__half2*)(ao + (tok0 + 8) * (NH * DVH) + col) =
            __floats2half2_rn(accO[j][2] * inv1, accO[j][3] * inv1);
    }
}

// ---------------- fp16 HMMA GEMM, 4-stage cp.async, optional split-K ------
#define STG_B   20480
#define SMEM_G  (4 * STG_B)   // 81920

template<int OMODE, bool BIAS, bool RES, bool SWISH, bool SPLITK>
__global__ void __launch_bounds__(256, 2)
f_gemm(const half_t* __restrict__ A, const half_t* __restrict__ B,
       float* __restrict__ Cf, half_t* __restrict__ Ch,
       const float* __restrict__ bias, const float* __restrict__ res,
       int K, int lda, int ldb, int ldc, float alpha)
{
    extern __shared__ char sm[];
    const uint32_t smb = smem_u32(sm);
    const int tid = threadIdx.x, wid = tid >> 5, lane = tid & 31;
    const int wm = wid & 1, wn = wid >> 1;
    const long bm0 = (long)blockIdx.y * 128;
    const long bn0 = (long)blockIdx.x * 128;
    long zoff = 0;
    if (SPLITK) {
        A += (long)blockIdx.z * K;
        B += (long)blockIdx.z * K;
        zoff = (long)blockIdx.z * ((long)gridDim.y * 128) * ldc;
    }

    const int rr = tid >> 1;
    const int pq = (tid & 1) << 4;

    auto issue = [&](int k0, int stg) {
        const uint32_t base = smb + stg * STG_B;
        const half_t* as = A + (bm0 + rr) * (long)lda + k0 + pq;
        uint32_t da = base + rr * 80 + pq * 2;
        cpa16(da, as); cpa16(da + 16, as + 8);
        const half_t* bs = B + (bn0 + rr) * (long)ldb + k0 + pq;
        uint32_t db = base + 10240 + rr * 80 + pq * 2;
        cpa16(db, bs); cpa16(db + 16, bs + 8);
    };

    float acc[4][4][4];
    #pragma unroll
    for (int i = 0; i < 4; i++)
        #pragma unroll
        for (int j = 0; j < 4; j++)
            #pragma unroll
            for (int t = 0; t < 4; t++) acc[i][j][t] = 0.0f;

    auto mma_chunk = [&](int stg) {
        const uint32_t base = smb + stg * STG_B;
        #pragma unroll
        for (int ks = 0; ks < 2; ks++) {
            const int kk = ks * 16;
            uint32_t bfr[4][2];
            #pragma unroll
            for (int p = 0; p < 2; p++) {
                uint32_t bd = base + 10240 + (wn * 32 + p * 16 + (lane & 15)) * 80
                                   + (kk + (lane >> 4) * 8) * 2;
                uint32_t r[4];
                ldx4(r, bd);
                bfr[2*p][0] = r[0]; bfr[2*p][1] = r[2];
                bfr[2*p+1][0] = r[1]; bfr[2*p+1][1] = r[3];
            }
            #pragma unroll
            for (int mi = 0; mi < 4; mi++) {
                uint32_t afr[4];
                uint32_t ad = base + (wm * 64 + mi * 16 + (lane & 15)) * 80
                                   + (kk + (lane >> 4) * 8) * 2;
                ldx4(afr, ad);
                #pragma unroll
                for (int ni = 0; ni < 4; ni++)
                    mma_f16(acc[mi][ni], afr, bfr[ni]);
            }
        }
    };

    const int chunks = K >> 5;
    issue(0, 0); CP_COMMIT();
    issue(32, 1); CP_COMMIT();
    issue(64, 2); CP_COMMIT();
    for (int c = 0; c < chunks; c++) {
        const int rem = chunks - 1 - c;
        if (rem >= 2)      asm volatile("cp.async.wait_group 2;");
        else if (rem == 1) asm volatile("cp.async.wait_group 1;");
        else               asm volatile("cp.async.wait_group 0;");
        __syncthreads();
        if (c + 3 < chunks) { issue((c + 3) << 5, (c + 3) & 3); CP_COMMIT(); }
        mma_chunk(c & 3);
    }

    #pragma unroll
    for (int mi = 0; mi < 4; mi++) {
        #pragma unroll
        for (int ni = 0; ni < 4; ni++) {
            long n = bn0 + wn * 32 + ni * 8 + (lane & 3) * 2;
            #pragma unroll
            for (int hf = 0; hf < 2; hf++) {
                long m = bm0 + wm * 64 + mi * 16 + (lane >> 2) + hf * 8;
                float2 v;
                v.x = acc[mi][ni][hf * 2 + 0] * alpha;
                v.y = acc[mi][ni][hf * 2 + 1] * alpha;
                if (BIAS) {
                    float2 bb = *(const float2*)(bias + n);
                    v.x += bb.x; v.y += bb.y;
                }
                if (SWISH) {
                    v.x = v.x / (1.0f + __expf(-v.x));
                    v.y = v.y / (1.0f + __expf(-v.y));
                }
                if (RES) {
                    float2 rr2 = *(const float2*)(res + m * (long)ldc + n);
                    v.x += rr2.x; v.y += rr2.y;
                }
                const long o = zoff + m * (long)ldc + n;
                if (OMODE == 0) *(float2*)(Cf + o) = v;
                else            *(__half2*)(Ch + o) = __floats2half2_rn(v.x, v.y);
            }
        }
    }
}

// ---------------- host orchestration ----------------
extern "C" void kernel_launch(void* const* d_in, const int* in_sizes, int n_in,
                              void* d_out, int out_size) {
    const float* x     = (const float*)d_in[0];
    const float* ln1_g = (const float*)d_in[1];
    const float* ln1_b = (const float*)d_in[2];
    const float* Wqkv  = (const float*)d_in[3];
    const float* bqkv  = (const float*)d_in[4];
    const float* Wm    = (const float*)d_in[5];
    const float* bm    = (const float*)d_in[6];
    const float* ln2_g = (const float*)d_in[7];
    const float* ln2_b = (const float*)d_in[8];
    const float* W1    = (const float*)d_in[9];
    const float* b1    = (const float*)d_in[10];
    const float* W2    = (const float*)d_in[11];
    const float* b2    = (const float*)d_in[12];
    float* out = (float*)d_out;

    half_t *xnf, *wq, *wm, *w1, *w2, *qkf, *aof, *x2nf, *hf;
    float *x2, *part;
    cudaGetSymbolAddress((void**)&xnf,  g_xnf);
    cudaGetSymbolAddress((void**)&wq,   g_Wq);
    cudaGetSymbolAddress((void**)&wm,   g_Wmw);
    cudaGetSymbolAddress((void**)&w1,   g_W1w);
    cudaGetSymbolAddress((void**)&w2,   g_W2w);
    cudaGetSymbolAddress((void**)&qkf,  g_qkvf);
    cudaGetSymbolAddress((void**)&aof,  g_aof);
    cudaGetSymbolAddress((void**)&x2nf, g_x2nf);
    cudaGetSymbolAddress((void**)&hf,   g_hf);
    cudaGetSymbolAddress((void**)&x2,   g_x2);
    cudaGetSymbolAddress((void**)&part, g_part);

    cudaFuncSetAttribute(f_gemm<2,true,false,false,false>, cudaFuncAttributeMaxDynamicSharedMemorySize, SMEM_G);
    cudaFuncSetAttribute(f_gemm<0,false,false,false,true>, cudaFuncAttributeMaxDynamicSharedMemorySize, SMEM_G);
    cudaFuncSetAttribute(f_gemm<2,true,false,true,false>,  cudaFuncAttributeMaxDynamicSharedMemorySize, SMEM_G);
    cudaFuncSetAttribute(flash_attn, cudaFuncAttributeMaxDynamicSharedMemorySize, FA_SMEM);

    // 0) all weight converts in one launch
    convAll<<<T0+T1+T2+T3, dim3(32, 8)>>>(Wqkv, Wm, W1, W2, wq, wm, w1, w2);

    // 1) LN1 -> fp16
    ln_f16<<<NTOK, 128>>>(x, ln1_g, ln1_b, xnf);

    // 2) qkv = xn @ Wqkv + bqkv -> fp16   (4096 x 5120, K=512)
    f_gemm<2,true,false,false,false><<<dim3(QKVN/128, NTOK/128), 256, SMEM_G>>>(
        xnf, wq, nullptr, qkf, bqkv, nullptr, DIN, DIN, DIN, QKVN, 1.0f);

    // 3) fused attention -> ao fp16
    flash_attn<<<dim3(4, 16, 16), 256, FA_SMEM>>>(qkf, aof);

    // 4) Wm split-K x4 -> fp32 partials   (4096 x 512, K=4x1024)
    f_gemm<0,false,false,false,true><<<dim3(DIN/128, NTOK/128, 4), 256, SMEM_G>>>(
        aof, wm, part, nullptr, nullptr, nullptr, 1024, NH*DVH, NH*DVH, DIN, 1.0f);

    // 5) LN2 fused with partial reduction + residual
    ln2sum4<<<NTOK, 128>>>(part, x, bm, ln2_g, ln2_b, x2, x2nf);

    // 6) h = swish(x2n @ W1 + b1) -> fp16  (4096 x 2048, K=512)
    f_gemm<2,true,false,true,false><<<dim3(DEXP/128, NTOK/128), 256, SMEM_G>>>(
        x2nf, w1, nullptr, hf, b1, nullptr, DIN, DIN, DIN, DEXP, 1.0f);

    // 7) W2 split-K x2 -> fp32 partials   (4096 x 512, K=2x1024)
    f_gemm<0,false,false,false,true><<<dim3(DIN/128, NTOK/128, 2), 256, SMEM_G>>>(
        hf, w2, part, nullptr, nullptr, nullptr, 1024, DEXP, DEXP, DIN, 1.0f);

    // 8) out = p0 + p1 + b2 + x2
    final_add<<<NTOK, 128>>>(part, b2, x2, out);
}